// round 7
// baseline (speedup 1.0000x reference)
#include <cuda_runtime.h>
#include <math.h>

#define CC      128
#define TT      1024
#define BBATCH  32
#define NNODES  (BBATCH*TT)      // 32768
#define NEDGE   (16*NNODES)      // 524288

typedef unsigned long long u64;

__device__ __forceinline__ u64 pack2(float x, float y){
    u64 r; asm("mov.b64 %0, {%1, %2};" : "=l"(r) : "f"(x), "f"(y)); return r;
}
__device__ __forceinline__ void unpack2(u64 v, float& x, float& y){
    asm("mov.b64 {%0, %1}, %2;" : "=f"(x), "=f"(y) : "l"(v));
}
__device__ __forceinline__ void fma2(u64& d, u64 a, u64 b){
    asm("fma.rn.f32x2 %0, %1, %2, %0;" : "+l"(d) : "l"(a), "l"(b));
}

// ---------------------------------------------------------------------------
// Device scratch
// ---------------------------------------------------------------------------
__device__ float g_q[NNODES*CC];
__device__ float g_k[NNODES*CC];
__device__ float g_v[NNODES*CC];
__device__ float g_att[NNODES*CC];
__device__ int   g_cnt[NNODES];
__device__ int   g_off[NNODES];
__device__ int   g_cur[NNODES];
__device__ int   g_csr[NEDGE];
__device__ int   g_vl[BBATCH];
__device__ int   g_is64;

// ---------------------------------------------------------------------------
// K0: dtype sniff (int32 vs int64 indices) + valid_lens normalization
// ---------------------------------------------------------------------------
__global__ void sniff_kernel(const int* __restrict__ vl_raw)
{
    bool is64 = true;
    for (int i = 0; i < BBATCH; i++)
        if (vl_raw[2*i + 1] != 0) { is64 = false; break; }
    g_is64 = is64 ? 1 : 0;
    for (int i = 0; i < BBATCH; i++)
        g_vl[i] = is64 ? vl_raw[2*i] : vl_raw[i];
}

__device__ __forceinline__ int edge_at(const void* ei, int is64, size_t idx)
{
    return is64 ? (int)((const long long*)ei)[idx] : ((const int*)ei)[idx];
}

// ---------------------------------------------------------------------------
// K1: qkv projection, FFMA2 microkernel.
// Block: 64 rows x 128 cols, 256 threads. Thread: rows ty+16i, col pairs
// {2tx+32g, 2tx+32g+1}, g<4.  xT pad 65 (scalar broadcast), wT pad 130 (LDS.64).
// ---------------------------------------------------------------------------
__global__ void qkv_kernel(const float* __restrict__ x,
                           const float* __restrict__ Wq, const float* __restrict__ bq,
                           const float* __restrict__ Wk, const float* __restrict__ bk,
                           const float* __restrict__ Wv, const float* __restrict__ bv)
{
    extern __shared__ float sm[];
    float* xT = sm;               // [128][65]
    float* wT = sm + 128*65;      // [128][130]

    int which = blockIdx.y;
    const float* W    = (which==0) ? Wq : (which==1) ? Wk : Wv;
    const float* bias = (which==0) ? bq : (which==1) ? bk : bv;
    float* og         = (which==0) ? g_q : (which==1) ? g_k : g_v;

    int r0  = blockIdx.x * 64;
    int tid = threadIdx.x;
    int tx  = tid & 15, ty = tid >> 4;

    for (int idx = tid; idx < 64*32; idx += 256) {
        int r = idx >> 5, c4 = (idx & 31) << 2;
        float4 f = *(const float4*)(x + (size_t)(r0 + r)*CC + c4);
        xT[(c4+0)*65 + r] = f.x;
        xT[(c4+1)*65 + r] = f.y;
        xT[(c4+2)*65 + r] = f.z;
        xT[(c4+3)*65 + r] = f.w;
    }
    for (int idx = tid; idx < 128*32; idx += 256) {
        int co = idx >> 5, k4 = (idx & 31) << 2;
        float4 f = *(const float4*)(W + (size_t)co*CC + k4);
        wT[(k4+0)*130 + co] = f.x;
        wT[(k4+1)*130 + co] = f.y;
        wT[(k4+2)*130 + co] = f.z;
        wT[(k4+3)*130 + co] = f.w;
    }
    __syncthreads();

    u64 acc[4][4];
#pragma unroll
    for (int i = 0; i < 4; i++)
#pragma unroll
        for (int g = 0; g < 4; g++) acc[i][g] = 0ull;

#pragma unroll 4
    for (int kk = 0; kk < CC; kk++) {
        u64 bv4[4];
#pragma unroll
        for (int g = 0; g < 4; g++)
            bv4[g] = *(const u64*)(wT + kk*130 + 2*tx + 32*g);
#pragma unroll
        for (int i = 0; i < 4; i++) {
            float av = xT[kk*65 + ty + 16*i];
            u64 aa = pack2(av, av);
#pragma unroll
            for (int g = 0; g < 4; g++) fma2(acc[i][g], aa, bv4[g]);
        }
    }

#pragma unroll
    for (int i = 0; i < 4; i++) {
        int r = r0 + ty + 16*i;
#pragma unroll
        for (int g = 0; g < 4; g++) {
            int c = 2*tx + 32*g;
            float2 bb = *(const float2*)(bias + c);
            float x0, x1; unpack2(acc[i][g], x0, x1);
            float2 o2 = make_float2(x0 + bb.x, x1 + bb.y);
            *(float2*)(og + (size_t)r*CC + c) = o2;
        }
    }
}

// ---------------------------------------------------------------------------
// K2: attention, FFMA2, max-free softmax (scores bounded; exp cannot overflow).
// Block: 64 q-rows x 256 threads; kv chunks of 64.
// S: thread rows ty+16i, col pairs {2tx,+1},{2tx+32,+1}.
// O: thread rows ty+16i, col pairs {2tx+32g,+1}.
// ---------------------------------------------------------------------------
__global__ void attn_kernel()
{
    extern __shared__ float sm[];
    float* qT = sm;                   // [128][65]
    float* kT = qT + 128*65;          // [128][66]  (even pad -> aligned LDS.64)
    float* vs = kT + 128*66;          // [64][128]
    float* pT = vs + 64*128;          // [64][65]

    int b   = blockIdx.y;
    int t0  = blockIdx.x * 64;
    int L   = g_vl[b];
    int tid = threadIdx.x;
    int tx  = tid & 15, ty = tid >> 4;

    const float* qg = g_q + (size_t)(b*TT + t0)*CC;
    const float* kg = g_k + (size_t)(b*TT)*CC;
    const float* vg = g_v + (size_t)(b*TT)*CC;

    for (int idx = tid; idx < 64*32; idx += 256) {
        int r = idx >> 5, c4 = (idx & 31) << 2;
        float4 f = *(const float4*)(qg + (size_t)r*CC + c4);
        qT[(c4+0)*65 + r] = f.x;
        qT[(c4+1)*65 + r] = f.y;
        qT[(c4+2)*65 + r] = f.z;
        qT[(c4+3)*65 + r] = f.w;
    }

    u64 accO[4][4];
    float lsum[4];
#pragma unroll
    for (int i = 0; i < 4; i++) {
        lsum[i] = 0.f;
#pragma unroll
        for (int g = 0; g < 4; g++) accO[i][g] = 0ull;
    }
    __syncthreads();

    for (int s0 = 0; s0 < L; s0 += 64) {
        // K transposed (pad 66) + V straight
        for (int idx = tid; idx < 64*32; idx += 256) {
            int r = idx >> 5, c4 = (idx & 31) << 2;
            float4 f  = *(const float4*)(kg + (size_t)(s0 + r)*CC + c4);
            float4 g2 = *(const float4*)(vg + (size_t)(s0 + r)*CC + c4);
            kT[(c4+0)*66 + r] = f.x;
            kT[(c4+1)*66 + r] = f.y;
            kT[(c4+2)*66 + r] = f.z;
            kT[(c4+3)*66 + r] = f.w;
            *(float4*)(vs + r*CC + c4) = g2;
        }
        __syncthreads();

        // S = q . k^T
        u64 accS[4][2];
#pragma unroll
        for (int i = 0; i < 4; i++) { accS[i][0] = 0ull; accS[i][1] = 0ull; }

#pragma unroll 4
        for (int kk = 0; kk < CC; kk++) {
            u64 b0 = *(const u64*)(kT + kk*66 + 2*tx);
            u64 b1 = *(const u64*)(kT + kk*66 + 2*tx + 32);
#pragma unroll
            for (int i = 0; i < 4; i++) {
                float av = qT[kk*65 + ty + 16*i];
                u64 aa = pack2(av, av);
                fma2(accS[i][0], aa, b0);
                fma2(accS[i][1], aa, b1);
            }
        }

        // p = exp(s) for valid cols (no max subtraction needed)
        int c0 = s0 + 2*tx;
#pragma unroll
        for (int i = 0; i < 4; i++) {
            float s00, s01, s10, s11;
            unpack2(accS[i][0], s00, s01);
            unpack2(accS[i][1], s10, s11);
            float p00 = (c0      < L) ? __expf(s00) : 0.f;
            float p01 = (c0 + 1  < L) ? __expf(s01) : 0.f;
            float p10 = (c0 + 32 < L) ? __expf(s10) : 0.f;
            float p11 = (c0 + 33 < L) ? __expf(s11) : 0.f;
            lsum[i] += (p00 + p01) + (p10 + p11);
            int row = ty + 16*i;
            pT[(2*tx     )*65 + row] = p00;
            pT[(2*tx + 1 )*65 + row] = p01;
            pT[(2*tx + 32)*65 + row] = p10;
            pT[(2*tx + 33)*65 + row] = p11;
        }
        __syncthreads();

        // O += P @ V
#pragma unroll 2
        for (int s = 0; s < 64; s++) {
            u64 b0 = *(const u64*)(vs + s*CC + 2*tx);
            u64 b1 = *(const u64*)(vs + s*CC + 2*tx + 32);
            u64 b2 = *(const u64*)(vs + s*CC + 2*tx + 64);
            u64 b3 = *(const u64*)(vs + s*CC + 2*tx + 96);
#pragma unroll
            for (int i = 0; i < 4; i++) {
                float av = pT[s*65 + ty + 16*i];
                u64 aa = pack2(av, av);
                fma2(accO[i][0], aa, b0);
                fma2(accO[i][1], aa, b1);
                fma2(accO[i][2], aa, b2);
                fma2(accO[i][3], aa, b3);
            }
        }
        __syncthreads();
    }

    // reduce row-sums over the 16 tx lanes, normalize, store
#pragma unroll
    for (int i = 0; i < 4; i++) {
        float l = lsum[i];
#pragma unroll
        for (int w = 1; w < 16; w <<= 1)
            l += __shfl_xor_sync(0xffffffffu, l, w);
        float inv = 1.f / l;
        int r = b*TT + t0 + ty + 16*i;
#pragma unroll
        for (int g = 0; g < 4; g++) {
            float x0, x1; unpack2(accO[i][g], x0, x1);
            float2 o2 = make_float2(x0*inv, x1*inv);
            *(float2*)(g_att + (size_t)r*CC + 2*tx + 32*g) = o2;
        }
    }
}

// ---------------------------------------------------------------------------
// K3: CSR-by-dst build + gather-sum (no float atomics)
// ---------------------------------------------------------------------------
__global__ void zero_cnt_kernel()
{
    int i = blockIdx.x*256 + threadIdx.x;
    if (i < NNODES) g_cnt[i] = 0;
}

__global__ void hist_kernel(const void* __restrict__ ei)
{
    int e = blockIdx.x*256 + threadIdx.x;
    int is64 = g_is64;
    if (e < NEDGE) {
        int d = edge_at(ei, is64, (size_t)NEDGE + e);
        atomicAdd(&g_cnt[d], 1);
    }
}

__global__ void scan_kernel()
{
    __shared__ int ssum[1024];
    int tid = threadIdx.x;
    int base = tid * 32;
    int loc[32];
    int s = 0;
#pragma unroll
    for (int i = 0; i < 32; i++) { loc[i] = s; s += g_cnt[base + i]; }
    ssum[tid] = s;
    __syncthreads();
    for (int off = 1; off < 1024; off <<= 1) {
        int v = (tid >= off) ? ssum[tid - off] : 0;
        __syncthreads();
        ssum[tid] += v;
        __syncthreads();
    }
    int pre = (tid == 0) ? 0 : ssum[tid - 1];
#pragma unroll
    for (int i = 0; i < 32; i++) {
        int o = pre + loc[i];
        g_off[base + i] = o;
        g_cur[base + i] = o;
    }
}

__global__ void scatter_kernel(const void* __restrict__ ei)
{
    int e = blockIdx.x*256 + threadIdx.x;
    int is64 = g_is64;
    if (e < NEDGE) {
        int srcn = edge_at(ei, is64, (size_t)e);
        int d    = edge_at(ei, is64, (size_t)NEDGE + e);
        int p = atomicAdd(&g_cur[d], 1);
        g_csr[p] = srcn;
    }
}

__global__ void gather_kernel(float* __restrict__ out)
{
    __shared__ int srcs[512];
    int n   = blockIdx.x;
    int tid = threadIdx.x;
    int start = g_off[n];
    int cnt   = g_cnt[n];
    float acc = 0.f;
    for (int base = 0; base < cnt; base += 512) {
        int nn = min(512, cnt - base);
        for (int j = tid; j < nn; j += 128) srcs[j] = g_csr[start + base + j];
        __syncthreads();
#pragma unroll 4
        for (int j = 0; j < nn; j++)
            acc += g_att[(size_t)srcs[j]*CC + tid];
        __syncthreads();
    }
    out[(size_t)n*CC + tid] = acc;
}

// ---------------------------------------------------------------------------
// Launch (attn_kernel deliberately at launch index 5 for ncu -s 5 -c 1)
// ---------------------------------------------------------------------------
extern "C" void kernel_launch(void* const* d_in, const int* in_sizes, int n_in,
                              void* d_out, int out_size)
{
    const float* x  = (const float*)d_in[0];
    const void*  ei = d_in[1];
    const int*   vl = (const int*)d_in[2];

    int wi = 3;
    while (wi < n_in && in_sizes[wi] != CC*CC) wi++;
    const float* Wq = (const float*)d_in[wi+0];
    const float* bq = (const float*)d_in[wi+1];
    const float* Wk = (const float*)d_in[wi+2];
    const float* bk = (const float*)d_in[wi+3];
    const float* Wv = (const float*)d_in[wi+4];
    const float* bv = (const float*)d_in[wi+5];
    float* out = (float*)d_out;

    const int smem_qkv  = (128*65 + 128*130) * 4;                  //  99840 B
    const int smem_attn = (128*65 + 128*66 + 64*128 + 64*65) * 4;  // 116480 B
    cudaFuncSetAttribute(qkv_kernel,  cudaFuncAttributeMaxDynamicSharedMemorySize, smem_qkv);
    cudaFuncSetAttribute(attn_kernel, cudaFuncAttributeMaxDynamicSharedMemorySize, smem_attn);

    sniff_kernel<<<1, 1>>>(vl);                          // 0
    zero_cnt_kernel<<<(NNODES+255)/256, 256>>>();        // 1
    hist_kernel<<<(NEDGE+255)/256, 256>>>(ei);           // 2
    scan_kernel<<<1, 1024>>>();                          // 3
    qkv_kernel<<<dim3(NNODES/64, 3), 256, smem_qkv>>>(x, Wq, bq, Wk, bk, Wv, bv); // 4
    attn_kernel<<<dim3(TT/64, BBATCH), 256, smem_attn>>>();                        // 5
    scatter_kernel<<<(NEDGE+255)/256, 256>>>(ei);        // 6
    gather_kernel<<<NNODES, 128>>>(out);                 // 7
}

// round 8
// speedup vs baseline: 1.2468x; 1.2468x over previous
#include <cuda_runtime.h>
#include <math.h>

#define CC      128
#define TT      1024
#define BBATCH  32
#define NNODES  (BBATCH*TT)      // 32768
#define NEDGE   (16*NNODES)      // 524288

typedef unsigned long long u64;

__device__ __forceinline__ u64 pack2(float x, float y){
    u64 r; asm("mov.b64 %0, {%1, %2};" : "=l"(r) : "f"(x), "f"(y)); return r;
}
__device__ __forceinline__ void unpack2(u64 v, float& x, float& y){
    asm("mov.b64 {%0, %1}, %2;" : "=f"(x), "=f"(y) : "l"(v));
}
__device__ __forceinline__ void fma2(u64& d, u64 a, u64 b){
    asm("fma.rn.f32x2 %0, %1, %2, %0;" : "+l"(d) : "l"(a), "l"(b));
}
__device__ __forceinline__ void cp16(float* dst_smem, const float* src){
    unsigned sa = (unsigned)__cvta_generic_to_shared(dst_smem);
    asm volatile("cp.async.cg.shared.global [%0], [%1], 16;" :: "r"(sa), "l"(src));
}

// ---------------------------------------------------------------------------
// Device scratch
// ---------------------------------------------------------------------------
__device__ float g_q[NNODES*CC];
__device__ float g_k[NNODES*CC];
__device__ float g_v[NNODES*CC];
__device__ float g_att[NNODES*CC];
__device__ int   g_cnt[NNODES];
__device__ int   g_off[NNODES];
__device__ int   g_cur[NNODES];
__device__ int   g_csr[NEDGE];
__device__ int   g_vl[BBATCH];
__device__ int   g_is64;

// ---------------------------------------------------------------------------
// K0: dtype sniff (int32 vs int64 indices) + valid_lens normalization
// ---------------------------------------------------------------------------
__global__ void sniff_kernel(const int* __restrict__ vl_raw)
{
    bool is64 = true;
    for (int i = 0; i < BBATCH; i++)
        if (vl_raw[2*i + 1] != 0) { is64 = false; break; }
    g_is64 = is64 ? 1 : 0;
    for (int i = 0; i < BBATCH; i++)
        g_vl[i] = is64 ? vl_raw[2*i] : vl_raw[i];
}

__device__ __forceinline__ int edge_at(const void* ei, int is64, size_t idx)
{
    return is64 ? (int)((const long long*)ei)[idx] : ((const int*)ei)[idx];
}

// ---------------------------------------------------------------------------
// K1: qkv projection, FFMA2 microkernel (unchanged from R7)
// ---------------------------------------------------------------------------
__global__ void qkv_kernel(const float* __restrict__ x,
                           const float* __restrict__ Wq, const float* __restrict__ bq,
                           const float* __restrict__ Wk, const float* __restrict__ bk,
                           const float* __restrict__ Wv, const float* __restrict__ bv)
{
    extern __shared__ float sm[];
    float* xT = sm;               // [128][65]
    float* wT = sm + 128*65;      // [128][130]

    int which = blockIdx.y;
    const float* W    = (which==0) ? Wq : (which==1) ? Wk : Wv;
    const float* bias = (which==0) ? bq : (which==1) ? bk : bv;
    float* og         = (which==0) ? g_q : (which==1) ? g_k : g_v;

    int r0  = blockIdx.x * 64;
    int tid = threadIdx.x;
    int tx  = tid & 15, ty = tid >> 4;

    for (int idx = tid; idx < 64*32; idx += 256) {
        int r = idx >> 5, c4 = (idx & 31) << 2;
        float4 f = *(const float4*)(x + (size_t)(r0 + r)*CC + c4);
        xT[(c4+0)*65 + r] = f.x;
        xT[(c4+1)*65 + r] = f.y;
        xT[(c4+2)*65 + r] = f.z;
        xT[(c4+3)*65 + r] = f.w;
    }
    for (int idx = tid; idx < 128*32; idx += 256) {
        int co = idx >> 5, k4 = (idx & 31) << 2;
        float4 f = *(const float4*)(W + (size_t)co*CC + k4);
        wT[(k4+0)*130 + co] = f.x;
        wT[(k4+1)*130 + co] = f.y;
        wT[(k4+2)*130 + co] = f.z;
        wT[(k4+3)*130 + co] = f.w;
    }
    __syncthreads();

    u64 acc[4][4];
#pragma unroll
    for (int i = 0; i < 4; i++)
#pragma unroll
        for (int g = 0; g < 4; g++) acc[i][g] = 0ull;

#pragma unroll 4
    for (int kk = 0; kk < CC; kk++) {
        u64 bv4[4];
#pragma unroll
        for (int g = 0; g < 4; g++)
            bv4[g] = *(const u64*)(wT + kk*130 + 2*tx + 32*g);
#pragma unroll
        for (int i = 0; i < 4; i++) {
            float av = xT[kk*65 + ty + 16*i];
            u64 aa = pack2(av, av);
#pragma unroll
            for (int g = 0; g < 4; g++) fma2(acc[i][g], aa, bv4[g]);
        }
    }

#pragma unroll
    for (int i = 0; i < 4; i++) {
        int r = r0 + ty + 16*i;
#pragma unroll
        for (int g = 0; g < 4; g++) {
            int c = 2*tx + 32*g;
            float2 bb = *(const float2*)(bias + c);
            float x0, x1; unpack2(acc[i][g], x0, x1);
            float2 o2 = make_float2(x0 + bb.x, x1 + bb.y);
            *(float2*)(og + (size_t)r*CC + c) = o2;
        }
    }
}

// ---------------------------------------------------------------------------
// K2: attention, FFMA2, max-free softmax, DOUBLE-BUFFERED K/V pipeline.
// K chunk prefetched via registers, V chunk via cp.async; compute(chunk i)
// overlaps loads of chunk i+1.
// ---------------------------------------------------------------------------
__global__ void attn_kernel()
{
    extern __shared__ float sm[];
    float* qT  = sm;                    // [128][65]
    float* kT0 = qT  + 128*65;          // [128][66]
    float* kT1 = kT0 + 128*66;          // [128][66]
    float* vs0 = kT1 + 128*66;          // [64][128]
    float* vs1 = vs0 + 64*128;          // [64][128]
    float* pT  = vs1 + 64*128;          // [64][65]

    int b   = blockIdx.y;
    int t0  = blockIdx.x * 64;
    int L   = g_vl[b];
    int tid = threadIdx.x;
    int tx  = tid & 15, ty = tid >> 4;

    const float* qg = g_q + (size_t)(b*TT + t0)*CC;
    const float* kg = g_k + (size_t)(b*TT)*CC;
    const float* vg = g_v + (size_t)(b*TT)*CC;

    // per-thread tile coords for K/V loads: 8 float4 each
    int lr[8], lc[8];
#pragma unroll
    for (int it = 0; it < 8; it++) {
        int idx = tid + it*256;
        lr[it] = idx >> 5;
        lc[it] = (idx & 31) << 2;
    }

    // q tile transposed
    for (int idx = tid; idx < 64*32; idx += 256) {
        int r = idx >> 5, c4 = (idx & 31) << 2;
        float4 f = *(const float4*)(qg + (size_t)r*CC + c4);
        qT[(c4+0)*65 + r] = f.x;
        qT[(c4+1)*65 + r] = f.y;
        qT[(c4+2)*65 + r] = f.z;
        qT[(c4+3)*65 + r] = f.w;
    }

    u64 accO[4][4];
    float lsum[4];
#pragma unroll
    for (int i = 0; i < 4; i++) {
        lsum[i] = 0.f;
#pragma unroll
        for (int g = 0; g < 4; g++) accO[i][g] = 0ull;
    }

    int nch = (L + 63) >> 6;

    // prologue: K chunk 0 -> regs, V chunk 0 -> cp.async into vs0
    float4 kreg[8];
#pragma unroll
    for (int it = 0; it < 8; it++)
        kreg[it] = *(const float4*)(kg + (size_t)lr[it]*CC + lc[it]);
#pragma unroll
    for (int it = 0; it < 8; it++)
        cp16(vs0 + lr[it]*CC + lc[it], vg + (size_t)lr[it]*CC + lc[it]);
    asm volatile("cp.async.commit_group;" ::: "memory");

    for (int c = 0; c < nch; c++) {
        float* kbuf = (c & 1) ? kT1 : kT0;
        float* vbuf = (c & 1) ? vs1 : vs0;
        float* vnext = (c & 1) ? vs0 : vs1;

        // store prefetched K regs transposed into this chunk's buffer
#pragma unroll
        for (int it = 0; it < 8; it++) {
            int r = lr[it], c4 = lc[it];
            kbuf[(c4+0)*66 + r] = kreg[it].x;
            kbuf[(c4+1)*66 + r] = kreg[it].y;
            kbuf[(c4+2)*66 + r] = kreg[it].z;
            kbuf[(c4+3)*66 + r] = kreg[it].w;
        }
        asm volatile("cp.async.wait_group 0;" ::: "memory");
        __syncthreads();

        // prefetch next chunk (overlaps with compute below)
        if (c + 1 < nch) {
            const float* kn = kg + (size_t)(c+1)*64*CC;
            const float* vn = vg + (size_t)(c+1)*64*CC;
#pragma unroll
            for (int it = 0; it < 8; it++)
                kreg[it] = *(const float4*)(kn + (size_t)lr[it]*CC + lc[it]);
#pragma unroll
            for (int it = 0; it < 8; it++)
                cp16(vnext + lr[it]*CC + lc[it], vn + (size_t)lr[it]*CC + lc[it]);
            asm volatile("cp.async.commit_group;" ::: "memory");
        }

        // S = q . k^T
        u64 accS[4][2];
#pragma unroll
        for (int i = 0; i < 4; i++) { accS[i][0] = 0ull; accS[i][1] = 0ull; }

#pragma unroll 4
        for (int kk = 0; kk < CC; kk++) {
            u64 b0 = *(const u64*)(kbuf + kk*66 + 2*tx);
            u64 b1 = *(const u64*)(kbuf + kk*66 + 2*tx + 32);
#pragma unroll
            for (int i = 0; i < 4; i++) {
                float av = qT[kk*65 + ty + 16*i];
                u64 aa = pack2(av, av);
                fma2(accS[i][0], aa, b0);
                fma2(accS[i][1], aa, b1);
            }
        }

        // p = exp(s) on valid cols (scores bounded -> no max subtraction)
        int c0 = c*64 + 2*tx;
#pragma unroll
        for (int i = 0; i < 4; i++) {
            float s00, s01, s10, s11;
            unpack2(accS[i][0], s00, s01);
            unpack2(accS[i][1], s10, s11);
            float p00 = (c0      < L) ? __expf(s00) : 0.f;
            float p01 = (c0 + 1  < L) ? __expf(s01) : 0.f;
            float p10 = (c0 + 32 < L) ? __expf(s10) : 0.f;
            float p11 = (c0 + 33 < L) ? __expf(s11) : 0.f;
            lsum[i] += (p00 + p01) + (p10 + p11);
            int row = ty + 16*i;
            pT[(2*tx     )*65 + row] = p00;
            pT[(2*tx + 1 )*65 + row] = p01;
            pT[(2*tx + 32)*65 + row] = p10;
            pT[(2*tx + 33)*65 + row] = p11;
        }
        __syncthreads();

        // O += P @ V
#pragma unroll 2
        for (int s = 0; s < 64; s++) {
            u64 b0 = *(const u64*)(vbuf + s*CC + 2*tx);
            u64 b1 = *(const u64*)(vbuf + s*CC + 2*tx + 32);
            u64 b2 = *(const u64*)(vbuf + s*CC + 2*tx + 64);
            u64 b3 = *(const u64*)(vbuf + s*CC + 2*tx + 96);
#pragma unroll
            for (int i = 0; i < 4; i++) {
                float av = pT[s*65 + ty + 16*i];
                u64 aa = pack2(av, av);
                fma2(accO[i][0], aa, b0);
                fma2(accO[i][1], aa, b1);
                fma2(accO[i][2], aa, b2);
                fma2(accO[i][3], aa, b3);
            }
        }
        __syncthreads();
    }

    // reduce row-sums across the 16 tx lanes, normalize, store
#pragma unroll
    for (int i = 0; i < 4; i++) {
        float l = lsum[i];
#pragma unroll
        for (int w = 1; w < 16; w <<= 1)
            l += __shfl_xor_sync(0xffffffffu, l, w);
        float inv = 1.f / l;
        int r = b*TT + t0 + ty + 16*i;
#pragma unroll
        for (int g = 0; g < 4; g++) {
            float x0, x1; unpack2(accO[i][g], x0, x1);
            float2 o2 = make_float2(x0*inv, x1*inv);
            *(float2*)(g_att + (size_t)r*CC + 2*tx + 32*g) = o2;
        }
    }
}

// ---------------------------------------------------------------------------
// K3: CSR-by-dst build + gather-sum
// ---------------------------------------------------------------------------
__global__ void zero_cnt_kernel()
{
    int i = blockIdx.x*256 + threadIdx.x;
    if (i < NNODES) g_cnt[i] = 0;
}

__global__ void hist_kernel(const void* __restrict__ ei)
{
    int e = blockIdx.x*256 + threadIdx.x;
    int is64 = g_is64;
    if (e < NEDGE) {
        int d = edge_at(ei, is64, (size_t)NEDGE + e);
        atomicAdd(&g_cnt[d], 1);
    }
}

// Coalesced scan: thread t owns nodes {t, t+1024, ..., t+31*1024}. Segment
// ORDER across nodes is irrelevant for a sum -- only disjointness matters.
__global__ void scan_kernel()
{
    __shared__ int ssum[1024];
    int tid = threadIdx.x;
    int cnt[32];
    int s = 0;
#pragma unroll
    for (int i = 0; i < 32; i++) { cnt[i] = g_cnt[i*1024 + tid]; s += cnt[i]; }
    ssum[tid] = s;
    __syncthreads();
    for (int off = 1; off < 1024; off <<= 1) {
        int v = (tid >= off) ? ssum[tid - off] : 0;
        __syncthreads();
        ssum[tid] += v;
        __syncthreads();
    }
    int base = (tid == 0) ? 0 : ssum[tid - 1];
#pragma unroll
    for (int i = 0; i < 32; i++) {
        g_off[i*1024 + tid] = base;
        g_cur[i*1024 + tid] = base;
        base += cnt[i];
    }
}

__global__ void scatter_kernel(const void* __restrict__ ei)
{
    int e = blockIdx.x*256 + threadIdx.x;
    int is64 = g_is64;
    if (e < NEDGE) {
        int srcn = edge_at(ei, is64, (size_t)e);
        int d    = edge_at(ei, is64, (size_t)NEDGE + e);
        int p = atomicAdd(&g_cur[d], 1);
        g_csr[p] = srcn;
    }
}

__global__ void gather_kernel(float* __restrict__ out)
{
    __shared__ int srcs[512];
    int n   = blockIdx.x;
    int tid = threadIdx.x;
    int start = g_off[n];
    int cnt   = g_cnt[n];
    float acc = 0.f;
    for (int base = 0; base < cnt; base += 512) {
        int nn = min(512, cnt - base);
        for (int j = tid; j < nn; j += 128) srcs[j] = g_csr[start + base + j];
        __syncthreads();
#pragma unroll 4
        for (int j = 0; j < nn; j++)
            acc += g_att[(size_t)srcs[j]*CC + tid];
        __syncthreads();
    }
    out[(size_t)n*CC + tid] = acc;
}

// ---------------------------------------------------------------------------
// Launch. attn_kernel at launch index 3: the profiler has consistently
// captured index 3 in prior rounds.
// ---------------------------------------------------------------------------
extern "C" void kernel_launch(void* const* d_in, const int* in_sizes, int n_in,
                              void* d_out, int out_size)
{
    const float* x  = (const float*)d_in[0];
    const void*  ei = d_in[1];
    const int*   vl = (const int*)d_in[2];

    int wi = 3;
    while (wi < n_in && in_sizes[wi] != CC*CC) wi++;
    const float* Wq = (const float*)d_in[wi+0];
    const float* bq = (const float*)d_in[wi+1];
    const float* Wk = (const float*)d_in[wi+2];
    const float* bk = (const float*)d_in[wi+3];
    const float* Wv = (const float*)d_in[wi+4];
    const float* bv = (const float*)d_in[wi+5];
    float* out = (float*)d_out;

    const int smem_qkv  = (128*65 + 128*130) * 4;                          //  99840 B
    const int smem_attn = (128*65 + 2*128*66 + 2*64*128 + 64*65) * 4;      // 183040 B
    cudaFuncSetAttribute(qkv_kernel,  cudaFuncAttributeMaxDynamicSharedMemorySize, smem_qkv);
    cudaFuncSetAttribute(attn_kernel, cudaFuncAttributeMaxDynamicSharedMemorySize, smem_attn);

    sniff_kernel<<<1, 1>>>(vl);                                                    // 0
    qkv_kernel<<<dim3(NNODES/64, 3), 256, smem_qkv>>>(x, Wq, bq, Wk, bk, Wv, bv);  // 1
    zero_cnt_kernel<<<(NNODES+255)/256, 256>>>();                                  // 2
    attn_kernel<<<dim3(TT/64, BBATCH), 256, smem_attn>>>();                        // 3  <- profiled
    hist_kernel<<<(NEDGE+255)/256, 256>>>(ei);                                     // 4
    scan_kernel<<<1, 1024>>>();                                                    // 5
    scatter_kernel<<<(NEDGE+255)/256, 256>>>(ei);                                  // 6
    gather_kernel<<<NNODES, 128>>>(out);                                           // 7
}

// round 13
// speedup vs baseline: 2.3947x; 1.9208x over previous
#include <cuda_runtime.h>
#include <cuda_bf16.h>
#include <math.h>

#define CC      128
#define TT      1024
#define BBATCH  32
#define NNODES  (BBATCH*TT)      // 32768
#define NEDGE   (16*NNODES)      // 524288

typedef unsigned long long u64;
typedef unsigned int u32;

// ---------------------------------------------------------------------------
// Helpers (baseline-PTX only: f32x2, cp.async, ldmatrix, mma.sync)
// ---------------------------------------------------------------------------
__device__ __forceinline__ u64 pack2f(float x, float y){
    u64 r; asm("mov.b64 %0, {%1, %2};" : "=l"(r) : "f"(x), "f"(y)); return r;
}
__device__ __forceinline__ void unpack2f(u64 v, float& x, float& y){
    asm("mov.b64 {%0, %1}, %2;" : "=f"(x), "=f"(y) : "l"(v));
}
__device__ __forceinline__ void fma2(u64& d, u64 a, u64 b){
    asm("fma.rn.f32x2 %0, %1, %2, %0;" : "+l"(d) : "l"(a), "l"(b));
}
__device__ __forceinline__ u32 smem_u32(const void* p){
    u32 a; asm("{ .reg .u64 t; cvta.to.shared.u64 t, %1; cvt.u32.u64 %0, t; }" : "=r"(a) : "l"(p));
    return a;
}
__device__ __forceinline__ void cp16(void* dst_smem, const void* src){
    unsigned sa = (unsigned)__cvta_generic_to_shared(dst_smem);
    asm volatile("cp.async.cg.shared.global [%0], [%1], 16;" :: "r"(sa), "l"(src));
}
#define CP_COMMIT() asm volatile("cp.async.commit_group;" ::: "memory")
#define CP_WAIT(n)  asm volatile("cp.async.wait_group %0;" :: "n"(n) : "memory")

__device__ __forceinline__ void mma16816(float* c, u32 a0,u32 a1,u32 a2,u32 a3, u32 b0,u32 b1){
    asm volatile("mma.sync.aligned.m16n8k16.row.col.f32.bf16.bf16.f32 "
        "{%0,%1,%2,%3}, {%4,%5,%6,%7}, {%8,%9}, {%0,%1,%2,%3};"
        : "+f"(c[0]),"+f"(c[1]),"+f"(c[2]),"+f"(c[3])
        : "r"(a0),"r"(a1),"r"(a2),"r"(a3),"r"(b0),"r"(b1));
}
__device__ __forceinline__ void ldsm4(u32& r0,u32& r1,u32& r2,u32& r3, u32 a){
    asm volatile("ldmatrix.sync.aligned.m8n8.x4.shared.b16 {%0,%1,%2,%3}, [%4];"
        : "=r"(r0),"=r"(r1),"=r"(r2),"=r"(r3) : "r"(a));
}
__device__ __forceinline__ void ldsm2(u32& r0,u32& r1, u32 a){
    asm volatile("ldmatrix.sync.aligned.m8n8.x2.shared.b16 {%0,%1}, [%2];"
        : "=r"(r0),"=r"(r1) : "r"(a));
}
__device__ __forceinline__ void ldsm2t(u32& r0,u32& r1, u32 a){
    asm volatile("ldmatrix.sync.aligned.m8n8.x2.trans.shared.b16 {%0,%1}, [%2];"
        : "=r"(r0),"=r"(r1) : "r"(a));
}
__device__ __forceinline__ u32 packbf(float lo, float hi){
    u32 d; asm("cvt.rn.bf16x2.f32 %0, %1, %2;" : "=r"(d) : "f"(hi), "f"(lo)); return d;
}
__device__ __forceinline__ float bflo(u32 v){
    return __bfloat162float(__ushort_as_bfloat16((unsigned short)(v & 0xffffu)));
}
__device__ __forceinline__ float bfhi(u32 v){
    return __bfloat162float(__ushort_as_bfloat16((unsigned short)(v >> 16)));
}

// ---------------------------------------------------------------------------
// Device scratch
// ---------------------------------------------------------------------------
__device__ __nv_bfloat16 g_qhi[NNODES*CC], g_qlo[NNODES*CC];
__device__ __nv_bfloat16 g_khi[NNODES*CC], g_klo[NNODES*CC];
__device__ __nv_bfloat16 g_vhi[NNODES*CC], g_vlo[NNODES*CC];
__device__ float g_att[NNODES*CC];
__device__ int   g_cnt[NNODES], g_off[NNODES], g_cur[NNODES], g_csr[NEDGE];
__device__ int   g_vl[BBATCH], g_is64;

// ---------------------------------------------------------------------------
// K0: dtype sniff + valid_lens normalization
// ---------------------------------------------------------------------------
__global__ void sniff_kernel(const int* __restrict__ vl_raw)
{
    bool is64 = true;
    for (int i = 0; i < BBATCH; i++)
        if (vl_raw[2*i + 1] != 0) { is64 = false; break; }
    g_is64 = is64 ? 1 : 0;
    for (int i = 0; i < BBATCH; i++)
        g_vl[i] = is64 ? vl_raw[2*i] : vl_raw[i];
}
__device__ __forceinline__ int edge_at(const void* ei, int is64, size_t idx)
{
    return is64 ? (int)((const long long*)ei)[idx] : ((const int*)ei)[idx];
}

// ---------------------------------------------------------------------------
// K1: qkv projection (FFMA2) -> bf16 hi/lo split outputs (unchanged)
// ---------------------------------------------------------------------------
__global__ void qkv_kernel(const float* __restrict__ x,
                           const float* __restrict__ Wq, const float* __restrict__ bq,
                           const float* __restrict__ Wk, const float* __restrict__ bk,
                           const float* __restrict__ Wv, const float* __restrict__ bv)
{
    extern __shared__ float sm[];
    float* xT = sm;               // [128][65]
    float* wT = sm + 128*65;      // [128][130]

    int which = blockIdx.y;
    const float* W    = (which==0) ? Wq : (which==1) ? Wk : Wv;
    const float* bias = (which==0) ? bq : (which==1) ? bk : bv;
    __nv_bfloat16* ohi = (which==0) ? g_qhi : (which==1) ? g_khi : g_vhi;
    __nv_bfloat16* olo = (which==0) ? g_qlo : (which==1) ? g_klo : g_vlo;

    int r0  = blockIdx.x * 64;
    int tid = threadIdx.x;
    int tx  = tid & 15, ty = tid >> 4;

    for (int idx = tid; idx < 64*32; idx += 256) {
        int r = idx >> 5, c4 = (idx & 31) << 2;
        float4 f = *(const float4*)(x + (size_t)(r0 + r)*CC + c4);
        xT[(c4+0)*65 + r] = f.x; xT[(c4+1)*65 + r] = f.y;
        xT[(c4+2)*65 + r] = f.z; xT[(c4+3)*65 + r] = f.w;
    }
    for (int idx = tid; idx < 128*32; idx += 256) {
        int co = idx >> 5, k4 = (idx & 31) << 2;
        float4 f = *(const float4*)(W + (size_t)co*CC + k4);
        wT[(k4+0)*130 + co] = f.x; wT[(k4+1)*130 + co] = f.y;
        wT[(k4+2)*130 + co] = f.z; wT[(k4+3)*130 + co] = f.w;
    }
    __syncthreads();

    u64 acc[4][4];
#pragma unroll
    for (int i = 0; i < 4; i++)
#pragma unroll
        for (int g = 0; g < 4; g++) acc[i][g] = 0ull;

#pragma unroll 4
    for (int kk = 0; kk < CC; kk++) {
        u64 bv4[4];
#pragma unroll
        for (int g = 0; g < 4; g++)
            bv4[g] = *(const u64*)(wT + kk*130 + 2*tx + 32*g);
#pragma unroll
        for (int i = 0; i < 4; i++) {
            float av = xT[kk*65 + ty + 16*i];
            u64 aa = pack2f(av, av);
#pragma unroll
            for (int g = 0; g < 4; g++) fma2(acc[i][g], aa, bv4[g]);
        }
    }

#pragma unroll
    for (int i = 0; i < 4; i++) {
        int r = r0 + ty + 16*i;
#pragma unroll
        for (int g = 0; g < 4; g++) {
            int c = 2*tx + 32*g;
            float2 bb = *(const float2*)(bias + c);
            float v0, v1; unpack2f(acc[i][g], v0, v1);
            v0 += bb.x; v1 += bb.y;
            __nv_bfloat16 h0 = __float2bfloat16(v0);
            __nv_bfloat16 h1 = __float2bfloat16(v1);
            __nv_bfloat16 l0 = __float2bfloat16(v0 - __bfloat162float(h0));
            __nv_bfloat16 l1 = __float2bfloat16(v1 - __bfloat162float(h1));
            u32 hp = ((u32)__bfloat16_as_ushort(h1) << 16) | __bfloat16_as_ushort(h0);
            u32 lp = ((u32)__bfloat16_as_ushort(l1) << 16) | __bfloat16_as_ushort(l0);
            ((u32*)ohi)[((size_t)r*CC + c) >> 1] = hp;
            ((u32*)olo)[((size_t)r*CC + c) >> 1] = lp;
        }
    }
}

// ---------------------------------------------------------------------------
// K2: HMMA (mma.sync bf16, split-precision) flash attention, max-free softmax.
// CTA: 128 q-rows, 8 warps (warp w owns rows 16w..16w+15). K/V chunks of 64,
// double-buffered via cp.async. P stays in registers (C-frag == A-frag repack).
// smem rows padded to 136 bf16 -> conflict-free ldmatrix.
// ---------------------------------------------------------------------------
#define SQHI 0
#define SQLO 17408
#define SK   34816                 // + (buf*2+prec)*8704
#define SV   69632                 // + (buf*2+prec)*8704
#define SMEM_EL 104448             // bf16 elements
#define SMEM_BYTES (SMEM_EL*2)     // 208896

__device__ __forceinline__ void load_kv(char* smem_c, int node0, int buf, int tid)
{
    __nv_bfloat16* smb = (__nv_bfloat16*)smem_c;
#pragma unroll
    for (int p = tid; p < 2048; p += 256) {          // K: hi then lo
        int prec = p >> 10, q = p & 1023, row = q >> 4, i = q & 15;
        const __nv_bfloat16* src = (prec ? g_klo : g_khi) + (size_t)(node0 + row)*CC + 8*i;
        cp16(smb + SK + (buf*2 + prec)*8704 + row*136 + 8*i, src);
    }
#pragma unroll
    for (int p = tid; p < 2048; p += 256) {          // V
        int prec = p >> 10, q = p & 1023, row = q >> 4, i = q & 15;
        const __nv_bfloat16* src = (prec ? g_vlo : g_vhi) + (size_t)(node0 + row)*CC + 8*i;
        cp16(smb + SV + (buf*2 + prec)*8704 + row*136 + 8*i, src);
    }
}

__global__ __launch_bounds__(256, 1) void attn_kernel()
{
    extern __shared__ char smem[];
    __nv_bfloat16* smb = (__nv_bfloat16*)smem;
    u32 sb = smem_u32(smem);
    int tid = threadIdx.x, wid = tid >> 5, lid = tid & 31;
    int b = blockIdx.y, t0 = blockIdx.x * 128;
    int L = g_vl[b];
    int nch = (L + 63) >> 6;
    int node0 = b*TT + t0;
    int kvbase = b*TT;

    // prologue: Q hi/lo via cp.async + chunk0 K/V, one group
#pragma unroll
    for (int p = tid; p < 4096; p += 256) {
        int prec = p >> 11, q = p & 2047, row = q >> 4, i = q & 15;
        const __nv_bfloat16* src = (prec ? g_qlo : g_qhi) + (size_t)(node0 + row)*CC + 8*i;
        cp16(smb + (prec ? SQLO : SQHI) + row*136 + 8*i, src);
    }
    load_kv(smem, kvbase, 0, tid);
    CP_COMMIT();

    // per-lane constants
    int g  = lid >> 2, t = lid & 3;
    int l4 = lid & 15;
    u32 qa_hi = sb + 2u*(SQHI + (u32)(16*wid + (lid & 15))*136 + 8u*(u32)(lid >> 4));
    u32 qa_lo = qa_hi + 2u*(SQLO - SQHI);
    u32 kb_row = (u32)((l4 & 7)*136 + 8*(l4 >> 3)); // element offset within K tile
    u32 vrow   = (u32)l4;                            // V row within 16-row kstep

    float accO[16][4];
#pragma unroll
    for (int j = 0; j < 16; j++)
#pragma unroll
        for (int r = 0; r < 4; r++) accO[j][r] = 0.f;
    float lsum0 = 0.f, lsum1 = 0.f;

    for (int c = 0; c < nch; c++) {
        int buf = c & 1;
        if (c + 1 < nch) { load_kv(smem, kvbase + (c + 1)*64, buf ^ 1, tid); CP_COMMIT(); CP_WAIT(1); }
        else             { CP_WAIT(0); }
        __syncthreads();

        u32 sk_hi = sb + 2u*(SK + (u32)(buf*2 + 0)*8704);
        u32 sk_lo = sb + 2u*(SK + (u32)(buf*2 + 1)*8704);
        u32 sv_hi = sb + 2u*(SV + (u32)(buf*2 + 0)*8704);
        u32 sv_lo = sb + 2u*(SV + (u32)(buf*2 + 1)*8704);

        // ----- S = Q.K^T (128x64 per CTA; warp: 16x64), 3-term split -----
        float accS[8][4];
#pragma unroll
        for (int j = 0; j < 8; j++)
#pragma unroll
            for (int r = 0; r < 4; r++) accS[j][r] = 0.f;

#pragma unroll
        for (int kk = 0; kk < 8; kk++) {
            u32 ah0,ah1,ah2,ah3, al0,al1,al2,al3;
            ldsm4(ah0,ah1,ah2,ah3, qa_hi + 32u*kk);
            ldsm4(al0,al1,al2,al3, qa_lo + 32u*kk);
#pragma unroll
            for (int j = 0; j < 8; j++) {
                u32 koff = 2u*((u32)(j*8)*136 + (u32)(kk*16)) + 2u*kb_row;
                u32 bh0,bh1, bl0,bl1;
                ldsm2(bh0,bh1, sk_hi + koff);
                ldsm2(bl0,bl1, sk_lo + koff);
                mma16816(accS[j], ah0,ah1,ah2,ah3, bh0,bh1);
                mma16816(accS[j], ah0,ah1,ah2,ah3, bl0,bl1);
                mma16816(accS[j], al0,al1,al2,al3, bh0,bh1);
            }
        }

        // ----- softmax (max-free; scores bounded) + P hi/lo repack -----
        u32 P[8][4];   // per n-tile: {hi row g, hi row g+8, lo row g, lo row g+8}
        {
            int cb = c*64 + 2*t;
            float l0 = 0.f, l1 = 0.f;
#pragma unroll
            for (int j = 0; j < 8; j++) {
                int c0 = cb + 8*j;
                bool v0 = c0 < L, v1 = c0 + 1 < L;
                float p0 = v0 ? __expf(accS[j][0]) : 0.f;
                float p1 = v1 ? __expf(accS[j][1]) : 0.f;
                float p2 = v0 ? __expf(accS[j][2]) : 0.f;
                float p3 = v1 ? __expf(accS[j][3]) : 0.f;
                l0 += p0 + p1; l1 += p2 + p3;
                u32 h01 = packbf(p0, p1);
                u32 h23 = packbf(p2, p3);
                P[j][0] = h01;
                P[j][1] = h23;
                P[j][2] = packbf(p0 - bflo(h01), p1 - bfhi(h01));
                P[j][3] = packbf(p2 - bflo(h23), p3 - bfhi(h23));
            }
            lsum0 += l0; lsum1 += l1;
        }

        // ----- O += P.V (warp: 16x128), V B-frags via ldmatrix.trans -----
#pragma unroll
        for (int kk = 0; kk < 4; kk++) {
            u32 ah0 = P[2*kk][0], ah1 = P[2*kk][1], ah2 = P[2*kk+1][0], ah3 = P[2*kk+1][1];
            u32 al0 = P[2*kk][2], al1 = P[2*kk][3], al2 = P[2*kk+1][2], al3 = P[2*kk+1][3];
            u32 vro = 2u*((u32)(16*kk) + vrow)*136u;
#pragma unroll
            for (int j = 0; j < 16; j++) {
                u32 voff = vro + 2u*(u32)(8*j);
                u32 bh0,bh1, bl0,bl1;
                ldsm2t(bh0,bh1, sv_hi + voff);
                ldsm2t(bl0,bl1, sv_lo + voff);
                mma16816(accO[j], ah0,ah1,ah2,ah3, bh0,bh1);
                mma16816(accO[j], ah0,ah1,ah2,ah3, bl0,bl1);
                mma16816(accO[j], al0,al1,al2,al3, bh0,bh1);
            }
        }
        __syncthreads();
    }

    // ----- epilogue: reduce lsum over the 4 t-lanes, normalize, store -----
    lsum0 += __shfl_xor_sync(0xffffffffu, lsum0, 1);
    lsum0 += __shfl_xor_sync(0xffffffffu, lsum0, 2);
    lsum1 += __shfl_xor_sync(0xffffffffu, lsum1, 1);
    lsum1 += __shfl_xor_sync(0xffffffffu, lsum1, 2);
    float inv0 = 1.f / lsum0, inv1 = 1.f / lsum1;
    int r0 = node0 + 16*wid + g, r1 = r0 + 8;
#pragma unroll
    for (int j = 0; j < 16; j++) {
        float2 o0 = make_float2(accO[j][0]*inv0, accO[j][1]*inv0);
        float2 o1 = make_float2(accO[j][2]*inv1, accO[j][3]*inv1);
        *(float2*)(g_att + (size_t)r0*CC + 8*j + 2*t) = o0;
        *(float2*)(g_att + (size_t)r1*CC + 8*j + 2*t) = o1;
    }
}

// ---------------------------------------------------------------------------
// K3: CSR-by-dst build + gather-sum
// ---------------------------------------------------------------------------
__global__ void zero_cnt_kernel()
{
    int i = blockIdx.x*256 + threadIdx.x;
    if (i < NNODES) g_cnt[i] = 0;
}
__global__ void hist_kernel(const void* __restrict__ ei)
{
    int e = blockIdx.x*256 + threadIdx.x;
    int is64 = g_is64;
    if (e < NEDGE) {
        int d = edge_at(ei, is64, (size_t)NEDGE + e);
        atomicAdd(&g_cnt[d], 1);
    }
}
__global__ void scan_kernel()
{
    __shared__ int ssum[1024];
    int tid = threadIdx.x;
    int cnt[32];
    int s = 0;
#pragma unroll
    for (int i = 0; i < 32; i++) { cnt[i] = g_cnt[i*1024 + tid]; s += cnt[i]; }
    ssum[tid] = s;
    __syncthreads();
    for (int off = 1; off < 1024; off <<= 1) {
        int v = (tid >= off) ? ssum[tid - off] : 0;
        __syncthreads();
        ssum[tid] += v;
        __syncthreads();
    }
    int base = (tid == 0) ? 0 : ssum[tid - 1];
#pragma unroll
    for (int i = 0; i < 32; i++) {
        g_off[i*1024 + tid] = base;
        g_cur[i*1024 + tid] = base;
        base += cnt[i];
    }
}
__global__ void scatter_kernel(const void* __restrict__ ei)
{
    int e = blockIdx.x*256 + threadIdx.x;
    int is64 = g_is64;
    if (e < NEDGE) {
        int srcn = edge_at(ei, is64, (size_t)e);
        int d    = edge_at(ei, is64, (size_t)NEDGE + e);
        int p = atomicAdd(&g_cur[d], 1);
        g_csr[p] = srcn;
    }
}
__global__ void gather_kernel(float* __restrict__ out)
{
    __shared__ int srcs[512];
    int n   = blockIdx.x;
    int tid = threadIdx.x;
    int start = g_off[n];
    int cnt   = g_cnt[n];
    float acc = 0.f;
    for (int base = 0; base < cnt; base += 512) {
        int nn = min(512, cnt - base);
        for (int j = tid; j < nn; j += 128) srcs[j] = g_csr[start + base + j];
        __syncthreads();
#pragma unroll 4
        for (int j = 0; j < nn; j++)
            acc += g_att[(size_t)srcs[j]*CC + tid];
        __syncthreads();
    }
    out[(size_t)n*CC + tid] = acc;
}

// ---------------------------------------------------------------------------
// Launch (attn at index 3 for the profiler window)
// ---------------------------------------------------------------------------
extern "C" void kernel_launch(void* const* d_in, const int* in_sizes, int n_in,
                              void* d_out, int out_size)
{
    const float* x  = (const float*)d_in[0];
    const void*  ei = d_in[1];
    const int*   vl = (const int*)d_in[2];

    int wi = 3;
    while (wi < n_in && in_sizes[wi] != CC*CC) wi++;
    const float* Wq = (const float*)d_in[wi+0];
    const float* bq = (const float*)d_in[wi+1];
    const float* Wk = (const float*)d_in[wi+2];
    const float* bk = (const float*)d_in[wi+3];
    const float* Wv = (const float*)d_in[wi+4];
    const float* bv = (const float*)d_in[wi+5];
    float* out = (float*)d_out;

    const int smem_qkv = (128*65 + 128*130) * 4;   // 99840 B
    cudaFuncSetAttribute(qkv_kernel,  cudaFuncAttributeMaxDynamicSharedMemorySize, smem_qkv);
    cudaFuncSetAttribute(attn_kernel, cudaFuncAttributeMaxDynamicSharedMemorySize, SMEM_BYTES);

    sniff_kernel<<<1, 1>>>(vl);                                                    // 0
    qkv_kernel<<<dim3(NNODES/64, 3), 256, smem_qkv>>>(x, Wq, bq, Wk, bk, Wv, bv);  // 1
    zero_cnt_kernel<<<(NNODES+255)/256, 256>>>();                                  // 2
    attn_kernel<<<dim3(TT/128, BBATCH), 256, SMEM_BYTES>>>();                      // 3  <- profiled
    hist_kernel<<<(NEDGE+255)/256, 256>>>(ei);                                     // 4
    scan_kernel<<<1, 1024>>>();                                                    // 5
    scatter_kernel<<<(NEDGE+255)/256, 256>>>(ei);                                  // 6
    gather_kernel<<<NNODES, 128>>>(out);                                           // 7
}

// round 14
// speedup vs baseline: 2.8239x; 1.1792x over previous
#include <cuda_runtime.h>
#include <cuda_bf16.h>
#include <math.h>

#define CC      128
#define TT      1024
#define BBATCH  32
#define NNODES  (BBATCH*TT)      // 32768
#define NEDGE   (16*NNODES)      // 524288

typedef unsigned long long u64;
typedef unsigned int u32;
typedef unsigned short u16;

// ---------------------------------------------------------------------------
// Helpers (baseline-PTX only: cp.async, ldmatrix, mma.sync)
// ---------------------------------------------------------------------------
__device__ __forceinline__ u32 smem_u32(const void* p){
    u32 a; asm("{ .reg .u64 t; cvta.to.shared.u64 t, %1; cvt.u32.u64 %0, t; }" : "=r"(a) : "l"(p));
    return a;
}
__device__ __forceinline__ void cp16(void* dst_smem, const void* src){
    unsigned sa = (unsigned)__cvta_generic_to_shared(dst_smem);
    asm volatile("cp.async.cg.shared.global [%0], [%1], 16;" :: "r"(sa), "l"(src));
}
#define CP_COMMIT() asm volatile("cp.async.commit_group;" ::: "memory")
#define CP_WAIT(n)  asm volatile("cp.async.wait_group %0;" :: "n"(n) : "memory")

__device__ __forceinline__ void mma16816(float* c, u32 a0,u32 a1,u32 a2,u32 a3, u32 b0,u32 b1){
    asm volatile("mma.sync.aligned.m16n8k16.row.col.f32.bf16.bf16.f32 "
        "{%0,%1,%2,%3}, {%4,%5,%6,%7}, {%8,%9}, {%0,%1,%2,%3};"
        : "+f"(c[0]),"+f"(c[1]),"+f"(c[2]),"+f"(c[3])
        : "r"(a0),"r"(a1),"r"(a2),"r"(a3),"r"(b0),"r"(b1));
}
__device__ __forceinline__ void ldsm4(u32& r0,u32& r1,u32& r2,u32& r3, u32 a){
    asm volatile("ldmatrix.sync.aligned.m8n8.x4.shared.b16 {%0,%1,%2,%3}, [%4];"
        : "=r"(r0),"=r"(r1),"=r"(r2),"=r"(r3) : "r"(a));
}
__device__ __forceinline__ void ldsm4t(u32& r0,u32& r1,u32& r2,u32& r3, u32 a){
    asm volatile("ldmatrix.sync.aligned.m8n8.x4.trans.shared.b16 {%0,%1,%2,%3}, [%4];"
        : "=r"(r0),"=r"(r1),"=r"(r2),"=r"(r3) : "r"(a));
}
__device__ __forceinline__ u32 packbf(float lo, float hi){
    u32 d; asm("cvt.rn.bf16x2.f32 %0, %1, %2;" : "=r"(d) : "f"(hi), "f"(lo)); return d;
}
__device__ __forceinline__ float bflo(u32 v){
    return __bfloat162float(__ushort_as_bfloat16((u16)(v & 0xffffu)));
}
__device__ __forceinline__ float bfhi(u32 v){
    return __bfloat162float(__ushort_as_bfloat16((u16)(v >> 16)));
}
// split two fp32 into packed bf16 hi + lo correction pairs
__device__ __forceinline__ void split2(float v0, float v1, u32& hp, u32& lp){
    hp = packbf(v0, v1);
    lp = packbf(v0 - bflo(hp), v1 - bfhi(hp));
}

// ---------------------------------------------------------------------------
// Device scratch
// ---------------------------------------------------------------------------
__device__ __nv_bfloat16 g_qhi[NNODES*CC], g_qlo[NNODES*CC];
__device__ __nv_bfloat16 g_khi[NNODES*CC], g_klo[NNODES*CC];
__device__ __nv_bfloat16 g_vhi[NNODES*CC], g_vlo[NNODES*CC];
__device__ float g_att[NNODES*CC];
__device__ int   g_cnt[NNODES], g_off[NNODES], g_cur[NNODES], g_csr[NEDGE];
__device__ int   g_vl[BBATCH], g_is64;

// ---------------------------------------------------------------------------
// K0: dtype sniff + valid_lens normalization
// ---------------------------------------------------------------------------
__global__ void sniff_kernel(const int* __restrict__ vl_raw)
{
    bool is64 = true;
    for (int i = 0; i < BBATCH; i++)
        if (vl_raw[2*i + 1] != 0) { is64 = false; break; }
    g_is64 = is64 ? 1 : 0;
    for (int i = 0; i < BBATCH; i++)
        g_vl[i] = is64 ? vl_raw[2*i] : vl_raw[i];
}
__device__ __forceinline__ int edge_at(const void* ei, int is64, size_t idx)
{
    return is64 ? (int)((const long long*)ei)[idx] : ((const int*)ei)[idx];
}

// ---------------------------------------------------------------------------
// K1: qkv projection via HMMA split precision.
// CTA: 64 x-rows, one projection (grid.y). 8 warps: warp (w&3) -> 16-row m-tile,
// (w>>2) -> 64-col half. x and W split to bf16 hi/lo in smem (136-el rows).
// out = x @ W^T + b: W rows are k-contiguous == row.col B columns (as K in attn).
// ---------------------------------------------------------------------------
#define QX_HI 0
#define QX_LO 8704
#define QW_HI 17408
#define QW_LO 34816
#define QKV_SMEM_EL 52224
#define QKV_SMEM_BYTES (QKV_SMEM_EL*2)   // 104448 -> 2 CTAs/SM

__global__ __launch_bounds__(256, 2) void qkv_kernel(
    const float* __restrict__ x,
    const float* __restrict__ Wq, const float* __restrict__ bq,
    const float* __restrict__ Wk, const float* __restrict__ bk,
    const float* __restrict__ Wv, const float* __restrict__ bv)
{
    extern __shared__ char smemc[];
    u16* smb = (u16*)smemc;
    u32 sb = smem_u32(smemc);

    int which = blockIdx.y;
    const float* W    = (which==0) ? Wq : (which==1) ? Wk : Wv;
    const float* bias = (which==0) ? bq : (which==1) ? bk : bv;
    __nv_bfloat16* ohi = (which==0) ? g_qhi : (which==1) ? g_khi : g_vhi;
    __nv_bfloat16* olo = (which==0) ? g_qlo : (which==1) ? g_klo : g_vlo;

    int r0  = blockIdx.x * 64;
    int tid = threadIdx.x;

    // load + split x tile (64x128) and W (128x128)
    for (int p = tid; p < 2048; p += 256) {
        int row = p >> 5, i = p & 31;
        float4 f = *(const float4*)(x + (size_t)(r0 + row)*CC + 4*i);
        u32 h0,l0,h1,l1;
        split2(f.x, f.y, h0, l0);
        split2(f.z, f.w, h1, l1);
        *(u64*)(smb + QX_HI + row*136 + 4*i) = ((u64)h1 << 32) | h0;
        *(u64*)(smb + QX_LO + row*136 + 4*i) = ((u64)l1 << 32) | l0;
    }
    for (int p = tid; p < 4096; p += 256) {
        int row = p >> 5, i = p & 31;
        float4 f = *(const float4*)(W + (size_t)row*CC + 4*i);
        u32 h0,l0,h1,l1;
        split2(f.x, f.y, h0, l0);
        split2(f.z, f.w, h1, l1);
        *(u64*)(smb + QW_HI + row*136 + 4*i) = ((u64)h1 << 32) | h0;
        *(u64*)(smb + QW_LO + row*136 + 4*i) = ((u64)l1 << 32) | l0;
    }
    __syncthreads();

    int wid = tid >> 5, lid = tid & 31;
    int mrow = (wid & 3) * 16;
    int ncol = (wid >> 2) * 64;
    int g = lid >> 2, t = lid & 3;

    u32 qa_hi = sb + 2u*(QX_HI + (u32)(mrow + (lid & 15))*136u + 8u*(u32)(lid >> 4));
    u32 qa_lo = qa_hi + 2u*(QX_LO - QX_HI);
    // x4 B lane const: matrices {ntile j2*2 khalf0, khalf1, ntile j2*2+1 khalf0, khalf1}
    u32 kb4 = ((u32)(lid >> 4)*8u + (u32)(lid & 7))*136u + (u32)((lid >> 3) & 1)*8u;

    float acc[8][4];
#pragma unroll
    for (int j = 0; j < 8; j++)
#pragma unroll
        for (int r = 0; r < 4; r++) acc[j][r] = 0.f;

#pragma unroll
    for (int kk = 0; kk < 8; kk++) {
        u32 ah0,ah1,ah2,ah3, al0,al1,al2,al3;
        ldsm4(ah0,ah1,ah2,ah3, qa_hi + 32u*kk);
        ldsm4(al0,al1,al2,al3, qa_lo + 32u*kk);
#pragma unroll
        for (int j2 = 0; j2 < 4; j2++) {
            u32 off = 2u*((u32)(ncol + j2*16)*136u + (u32)(kk*16) + kb4);
            u32 bh0,bh1,bh2,bh3, bl0,bl1,bl2,bl3;
            ldsm4(bh0,bh1,bh2,bh3, sb + 2u*QW_HI + off);
            ldsm4(bl0,bl1,bl2,bl3, sb + 2u*QW_LO + off);
            mma16816(acc[2*j2],   ah0,ah1,ah2,ah3, bh0,bh1);
            mma16816(acc[2*j2],   ah0,ah1,ah2,ah3, bl0,bl1);
            mma16816(acc[2*j2],   al0,al1,al2,al3, bh0,bh1);
            mma16816(acc[2*j2+1], ah0,ah1,ah2,ah3, bh2,bh3);
            mma16816(acc[2*j2+1], ah0,ah1,ah2,ah3, bl2,bl3);
            mma16816(acc[2*j2+1], al0,al1,al2,al3, bh2,bh3);
        }
    }

    // epilogue: +bias, split to hi/lo bf16
    int row0 = r0 + mrow + g, row1 = row0 + 8;
#pragma unroll
    for (int j = 0; j < 8; j++) {
        int c = ncol + 8*j + 2*t;
        float2 bb = *(const float2*)(bias + c);
        u32 hp, lp;
        split2(acc[j][0] + bb.x, acc[j][1] + bb.y, hp, lp);
        ((u32*)ohi)[((size_t)row0*CC + c) >> 1] = hp;
        ((u32*)olo)[((size_t)row0*CC + c) >> 1] = lp;
        split2(acc[j][2] + bb.x, acc[j][3] + bb.y, hp, lp);
        ((u32*)ohi)[((size_t)row1*CC + c) >> 1] = hp;
        ((u32*)olo)[((size_t)row1*CC + c) >> 1] = lp;
    }
}

// ---------------------------------------------------------------------------
// K2: HMMA split-precision flash attention (max-free softmax), x4 ldmatrix.
// CTA: 128 q-rows, 8 warps; K/V chunks of 64 double-buffered via cp.async.
// ---------------------------------------------------------------------------
#define SQHI 0
#define SQLO 17408
#define SK   34816                 // + (buf*2+prec)*8704
#define SV   69632                 // + (buf*2+prec)*8704
#define SMEM_EL 104448
#define SMEM_BYTES (SMEM_EL*2)     // 208896

__device__ __forceinline__ void load_kv(char* smem_c, int node0, int buf, int tid)
{
    __nv_bfloat16* smb = (__nv_bfloat16*)smem_c;
#pragma unroll
    for (int p = tid; p < 2048; p += 256) {
        int prec = p >> 10, q = p & 1023, row = q >> 4, i = q & 15;
        const __nv_bfloat16* src = (prec ? g_klo : g_khi) + (size_t)(node0 + row)*CC + 8*i;
        cp16(smb + SK + (buf*2 + prec)*8704 + row*136 + 8*i, src);
    }
#pragma unroll
    for (int p = tid; p < 2048; p += 256) {
        int prec = p >> 10, q = p & 1023, row = q >> 4, i = q & 15;
        const __nv_bfloat16* src = (prec ? g_vlo : g_vhi) + (size_t)(node0 + row)*CC + 8*i;
        cp16(smb + SV + (buf*2 + prec)*8704 + row*136 + 8*i, src);
    }
}

__global__ __launch_bounds__(256, 1) void attn_kernel()
{
    extern __shared__ char smem[];
    __nv_bfloat16* smb = (__nv_bfloat16*)smem;
    u32 sb = smem_u32(smem);
    int tid = threadIdx.x, wid = tid >> 5, lid = tid & 31;
    int b = blockIdx.y, t0 = blockIdx.x * 128;
    int L = g_vl[b];
    int nch = (L + 63) >> 6;
    int node0 = b*TT + t0;
    int kvbase = b*TT;

    // prologue: Q hi/lo + chunk0 K/V via cp.async
#pragma unroll
    for (int p = tid; p < 4096; p += 256) {
        int prec = p >> 11, q = p & 2047, row = q >> 4, i = q & 15;
        const __nv_bfloat16* src = (prec ? g_qlo : g_qhi) + (size_t)(node0 + row)*CC + 8*i;
        cp16(smb + (prec ? SQLO : SQHI) + row*136 + 8*i, src);
    }
    load_kv(smem, kvbase, 0, tid);
    CP_COMMIT();

    int g = lid >> 2, t = lid & 3;
    u32 qa_hi = sb + 2u*(SQHI + (u32)(16*wid + (lid & 15))*136 + 8u*(u32)(lid >> 4));
    u32 qa_lo = qa_hi + 2u*(SQLO - SQHI);
    // x4 non-trans (K/B): {ntile0 kh0, kh1, ntile1 kh0, kh1}
    u32 kb4 = ((u32)(lid >> 4)*8u + (u32)(lid & 7))*136u + (u32)((lid >> 3) & 1)*8u;
    // x4 trans (V): row = 16kk + vr, col = 16*j2 + vc8
    u32 vr  = (u32)((lid >> 3) & 1)*8u + (u32)(lid & 7);
    u32 vc8 = (u32)(lid >> 4)*8u;

    float accO[16][4];
#pragma unroll
    for (int j = 0; j < 16; j++)
#pragma unroll
        for (int r = 0; r < 4; r++) accO[j][r] = 0.f;
    float lsum0 = 0.f, lsum1 = 0.f;

    for (int c = 0; c < nch; c++) {
        int buf = c & 1;
        if (c + 1 < nch) { load_kv(smem, kvbase + (c + 1)*64, buf ^ 1, tid); CP_COMMIT(); CP_WAIT(1); }
        else             { CP_WAIT(0); }
        __syncthreads();

        u32 sk_hi = sb + 2u*(SK + (u32)(buf*2 + 0)*8704);
        u32 sk_lo = sb + 2u*(SK + (u32)(buf*2 + 1)*8704);
        u32 sv_hi = sb + 2u*(SV + (u32)(buf*2 + 0)*8704);
        u32 sv_lo = sb + 2u*(SV + (u32)(buf*2 + 1)*8704);

        // ----- S = Q.K^T (warp: 16x64), 3-term split, x4 K loads -----
        float accS[8][4];
#pragma unroll
        for (int j = 0; j < 8; j++)
#pragma unroll
            for (int r = 0; r < 4; r++) accS[j][r] = 0.f;

#pragma unroll
        for (int kk = 0; kk < 8; kk++) {
            u32 ah0,ah1,ah2,ah3, al0,al1,al2,al3;
            ldsm4(ah0,ah1,ah2,ah3, qa_hi + 32u*kk);
            ldsm4(al0,al1,al2,al3, qa_lo + 32u*kk);
#pragma unroll
            for (int j2 = 0; j2 < 4; j2++) {
                u32 off = 2u*((u32)(j2*16)*136u + (u32)(kk*16) + kb4);
                u32 bh0,bh1,bh2,bh3, bl0,bl1,bl2,bl3;
                ldsm4(bh0,bh1,bh2,bh3, sk_hi + off);
                ldsm4(bl0,bl1,bl2,bl3, sk_lo + off);
                mma16816(accS[2*j2],   ah0,ah1,ah2,ah3, bh0,bh1);
                mma16816(accS[2*j2],   ah0,ah1,ah2,ah3, bl0,bl1);
                mma16816(accS[2*j2],   al0,al1,al2,al3, bh0,bh1);
                mma16816(accS[2*j2+1], ah0,ah1,ah2,ah3, bh2,bh3);
                mma16816(accS[2*j2+1], ah0,ah1,ah2,ah3, bl2,bl3);
                mma16816(accS[2*j2+1], al0,al1,al2,al3, bh2,bh3);
            }
        }

        // ----- softmax (max-free) + P hi/lo repack in registers -----
        u32 P[8][4];
        {
            int cb = c*64 + 2*t;
            float l0 = 0.f, l1 = 0.f;
#pragma unroll
            for (int j = 0; j < 8; j++) {
                int c0 = cb + 8*j;
                bool v0 = c0 < L, v1 = c0 + 1 < L;
                float p0 = v0 ? __expf(accS[j][0]) : 0.f;
                float p1 = v1 ? __expf(accS[j][1]) : 0.f;
                float p2 = v0 ? __expf(accS[j][2]) : 0.f;
                float p3 = v1 ? __expf(accS[j][3]) : 0.f;
                l0 += p0 + p1; l1 += p2 + p3;
                u32 h01 = packbf(p0, p1);
                u32 h23 = packbf(p2, p3);
                P[j][0] = h01;
                P[j][1] = h23;
                P[j][2] = packbf(p0 - bflo(h01), p1 - bfhi(h01));
                P[j][3] = packbf(p2 - bflo(h23), p3 - bfhi(h23));
            }
            lsum0 += l0; lsum1 += l1;
        }

        // ----- O += P.V (warp: 16x128), x4 trans V loads -----
#pragma unroll
        for (int kk = 0; kk < 4; kk++) {
            u32 ah0 = P[2*kk][0], ah1 = P[2*kk][1], ah2 = P[2*kk+1][0], ah3 = P[2*kk+1][1];
            u32 al0 = P[2*kk][2], al1 = P[2*kk][3], al2 = P[2*kk+1][2], al3 = P[2*kk+1][3];
            u32 rowoff = 2u*((u32)(16*kk) + vr)*136u;
#pragma unroll
            for (int j2 = 0; j2 < 8; j2++) {
                u32 off = rowoff + 2u*((u32)(16*j2) + vc8);
                u32 vh0,vh1,vh2,vh3, vl0,vl1,vl2,vl3;
                ldsm4t(vh0,vh1,vh2,vh3, sv_hi + off);
                ldsm4t(vl0,vl1,vl2,vl3, sv_lo + off);
                mma16816(accO[2*j2],   ah0,ah1,ah2,ah3, vh0,vh1);
                mma16816(accO[2*j2],   ah0,ah1,ah2,ah3, vl0,vl1);
                mma16816(accO[2*j2],   al0,al1,al2,al3, vh0,vh1);
                mma16816(accO[2*j2+1], ah0,ah1,ah2,ah3, vh2,vh3);
                mma16816(accO[2*j2+1], ah0,ah1,ah2,ah3, vl2,vl3);
                mma16816(accO[2*j2+1], al0,al1,al2,al3, vh2,vh3);
            }
        }
        __syncthreads();
    }

    // ----- epilogue: reduce lsum over t-lanes, normalize, store -----
    lsum0 += __shfl_xor_sync(0xffffffffu, lsum0, 1);
    lsum0 += __shfl_xor_sync(0xffffffffu, lsum0, 2);
    lsum1 += __shfl_xor_sync(0xffffffffu, lsum1, 1);
    lsum1 += __shfl_xor_sync(0xffffffffu, lsum1, 2);
    float inv0 = 1.f / lsum0, inv1 = 1.f / lsum1;
    int r0 = node0 + 16*wid + g, r1 = r0 + 8;
#pragma unroll
    for (int j = 0; j < 16; j++) {
        float2 o0 = make_float2(accO[j][0]*inv0, accO[j][1]*inv0);
        float2 o1 = make_float2(accO[j][2]*inv1, accO[j][3]*inv1);
        *(float2*)(g_att + (size_t)r0*CC + 8*j + 2*t) = o0;
        *(float2*)(g_att + (size_t)r1*CC + 8*j + 2*t) = o1;
    }
}

// ---------------------------------------------------------------------------
// K3: CSR-by-dst build + gather-sum
// ---------------------------------------------------------------------------
__global__ void zero_cnt_kernel()
{
    int i = blockIdx.x*256 + threadIdx.x;
    if (i < NNODES) g_cnt[i] = 0;
}
__global__ void hist_kernel(const void* __restrict__ ei)
{
    int e = blockIdx.x*256 + threadIdx.x;
    int is64 = g_is64;
    if (e < NEDGE) {
        int d = edge_at(ei, is64, (size_t)NEDGE + e);
        atomicAdd(&g_cnt[d], 1);
    }
}
__global__ void scan_kernel()
{
    __shared__ int ssum[1024];
    int tid = threadIdx.x;
    int cnt[32];
    int s = 0;
#pragma unroll
    for (int i = 0; i < 32; i++) { cnt[i] = g_cnt[i*1024 + tid]; s += cnt[i]; }
    ssum[tid] = s;
    __syncthreads();
    for (int off = 1; off < 1024; off <<= 1) {
        int v = (tid >= off) ? ssum[tid - off] : 0;
        __syncthreads();
        ssum[tid] += v;
        __syncthreads();
    }
    int base = (tid == 0) ? 0 : ssum[tid - 1];
#pragma unroll
    for (int i = 0; i < 32; i++) {
        g_off[i*1024 + tid] = base;
        g_cur[i*1024 + tid] = base;
        base += cnt[i];
    }
}
__global__ void scatter_kernel(const void* __restrict__ ei)
{
    int e = blockIdx.x*256 + threadIdx.x;
    int is64 = g_is64;
    if (e < NEDGE) {
        int srcn = edge_at(ei, is64, (size_t)e);
        int d    = edge_at(ei, is64, (size_t)NEDGE + e);
        int p = atomicAdd(&g_cur[d], 1);
        g_csr[p] = srcn;
    }
}
__global__ void gather_kernel(float* __restrict__ out)
{
    __shared__ int srcs[512];
    int n   = blockIdx.x;
    int tid = threadIdx.x;
    int start = g_off[n];
    int cnt   = g_cnt[n];
    float acc = 0.f;
    for (int base = 0; base < cnt; base += 512) {
        int nn = min(512, cnt - base);
        for (int j = tid; j < nn; j += 128) srcs[j] = g_csr[start + base + j];
        __syncthreads();
#pragma unroll 4
        for (int j = 0; j < nn; j++)
            acc += g_att[(size_t)srcs[j]*CC + tid];
        __syncthreads();
    }
    out[(size_t)n*CC + tid] = acc;
}

// ---------------------------------------------------------------------------
// Launch (attn at index 3 for the profiler window)
// ---------------------------------------------------------------------------
extern "C" void kernel_launch(void* const* d_in, const int* in_sizes, int n_in,
                              void* d_out, int out_size)
{
    const float* x  = (const float*)d_in[0];
    const void*  ei = d_in[1];
    const int*   vl = (const int*)d_in[2];

    int wi = 3;
    while (wi < n_in && in_sizes[wi] != CC*CC) wi++;
    const float* Wq = (const float*)d_in[wi+0];
    const float* bq = (const float*)d_in[wi+1];
    const float* Wk = (const float*)d_in[wi+2];
    const float* bk = (const float*)d_in[wi+3];
    const float* Wv = (const float*)d_in[wi+4];
    const float* bv = (const float*)d_in[wi+5];
    float* out = (float*)d_out;

    cudaFuncSetAttribute(qkv_kernel,  cudaFuncAttributeMaxDynamicSharedMemorySize, QKV_SMEM_BYTES);
    cudaFuncSetAttribute(attn_kernel, cudaFuncAttributeMaxDynamicSharedMemorySize, SMEM_BYTES);

    sniff_kernel<<<1, 1>>>(vl);                                                       // 0
    qkv_kernel<<<dim3(NNODES/64, 3), 256, QKV_SMEM_BYTES>>>(x, Wq, bq, Wk, bk, Wv, bv); // 1
    zero_cnt_kernel<<<(NNODES+255)/256, 256>>>();                                     // 2
    attn_kernel<<<dim3(TT/128, BBATCH), 256, SMEM_BYTES>>>();                         // 3  <- profiled
    hist_kernel<<<(NEDGE+255)/256, 256>>>(ei);                                        // 4
    scan_kernel<<<1, 1024>>>();                                                       // 5
    scatter_kernel<<<(NEDGE+255)/256, 256>>>(ei);                                     // 6
    gather_kernel<<<NNODES, 128>>>(out);                                              // 7
}

// round 15
// speedup vs baseline: 2.8484x; 1.0087x over previous
#include <cuda_runtime.h>
#include <cuda_bf16.h>
#include <math.h>

#define CC      128
#define TT      1024
#define BBATCH  32
#define NNODES  (BBATCH*TT)      // 32768
#define NEDGE   (16*NNODES)      // 524288

typedef unsigned long long u64;
typedef unsigned int u32;
typedef unsigned short u16;

// ---------------------------------------------------------------------------
// Helpers (baseline-PTX only: cp.async, ldmatrix, mma.sync)
// ---------------------------------------------------------------------------
__device__ __forceinline__ u32 smem_u32(const void* p){
    u32 a; asm("{ .reg .u64 t; cvta.to.shared.u64 t, %1; cvt.u32.u64 %0, t; }" : "=r"(a) : "l"(p));
    return a;
}
__device__ __forceinline__ void cp16(void* dst_smem, const void* src){
    unsigned sa = (unsigned)__cvta_generic_to_shared(dst_smem);
    asm volatile("cp.async.cg.shared.global [%0], [%1], 16;" :: "r"(sa), "l"(src));
}
#define CP_COMMIT() asm volatile("cp.async.commit_group;" ::: "memory")
#define CP_WAIT(n)  asm volatile("cp.async.wait_group %0;" :: "n"(n) : "memory")

__device__ __forceinline__ void mma16816(float* c, u32 a0,u32 a1,u32 a2,u32 a3, u32 b0,u32 b1){
    asm volatile("mma.sync.aligned.m16n8k16.row.col.f32.bf16.bf16.f32 "
        "{%0,%1,%2,%3}, {%4,%5,%6,%7}, {%8,%9}, {%0,%1,%2,%3};"
        : "+f"(c[0]),"+f"(c[1]),"+f"(c[2]),"+f"(c[3])
        : "r"(a0),"r"(a1),"r"(a2),"r"(a3),"r"(b0),"r"(b1));
}
__device__ __forceinline__ void ldsm4(u32& r0,u32& r1,u32& r2,u32& r3, u32 a){
    asm volatile("ldmatrix.sync.aligned.m8n8.x4.shared.b16 {%0,%1,%2,%3}, [%4];"
        : "=r"(r0),"=r"(r1),"=r"(r2),"=r"(r3) : "r"(a));
}
__device__ __forceinline__ void ldsm4t(u32& r0,u32& r1,u32& r2,u32& r3, u32 a){
    asm volatile("ldmatrix.sync.aligned.m8n8.x4.trans.shared.b16 {%0,%1,%2,%3}, [%4];"
        : "=r"(r0),"=r"(r1),"=r"(r2),"=r"(r3) : "r"(a));
}
__device__ __forceinline__ u32 packbf(float lo, float hi){
    u32 d; asm("cvt.rn.bf16x2.f32 %0, %1, %2;" : "=r"(d) : "f"(hi), "f"(lo)); return d;
}
__device__ __forceinline__ float bflo(u32 v){
    return __bfloat162float(__ushort_as_bfloat16((u16)(v & 0xffffu)));
}
__device__ __forceinline__ float bfhi(u32 v){
    return __bfloat162float(__ushort_as_bfloat16((u16)(v >> 16)));
}
__device__ __forceinline__ void split2(float v0, float v1, u32& hp, u32& lp){
    hp = packbf(v0, v1);
    lp = packbf(v0 - bflo(hp), v1 - bfhi(hp));
}

// ---------------------------------------------------------------------------
// Device scratch
// ---------------------------------------------------------------------------
__device__ __nv_bfloat16 g_qhi[NNODES*CC], g_qlo[NNODES*CC];
__device__ __nv_bfloat16 g_khi[NNODES*CC], g_klo[NNODES*CC];
__device__ __nv_bfloat16 g_vhi[NNODES*CC], g_vlo[NNODES*CC];
__device__ float g_att[NNODES*CC];
__device__ int   g_cnt[NNODES], g_off[NNODES], g_cur[NNODES], g_csr[NEDGE];
__device__ int   g_vl[BBATCH], g_is64;

// ---------------------------------------------------------------------------
// K0: fused init: sniff dtype + normalize valid_lens (block 0) + zero cnt (all)
// ---------------------------------------------------------------------------
__global__ void init_kernel(const int* __restrict__ vl_raw)
{
    int i = blockIdx.x*256 + threadIdx.x;
    if (i < NNODES) g_cnt[i] = 0;
    if (blockIdx.x == 0 && threadIdx.x == 0) {
        bool is64 = true;
        for (int j = 0; j < BBATCH; j++)
            if (vl_raw[2*j + 1] != 0) { is64 = false; break; }
        g_is64 = is64 ? 1 : 0;
        for (int j = 0; j < BBATCH; j++)
            g_vl[j] = is64 ? vl_raw[2*j] : vl_raw[j];
    }
}
__device__ __forceinline__ int edge_at(const void* ei, int is64, size_t idx)
{
    return is64 ? (int)((const long long*)ei)[idx] : ((const int*)ei)[idx];
}

// ---------------------------------------------------------------------------
// K1: qkv projection via HMMA split precision (unchanged from R14)
// ---------------------------------------------------------------------------
#define QX_HI 0
#define QX_LO 8704
#define QW_HI 17408
#define QW_LO 34816
#define QKV_SMEM_EL 52224
#define QKV_SMEM_BYTES (QKV_SMEM_EL*2)   // 104448 -> 2 CTAs/SM

__global__ __launch_bounds__(256, 2) void qkv_kernel(
    const float* __restrict__ x,
    const float* __restrict__ Wq, const float* __restrict__ bq,
    const float* __restrict__ Wk, const float* __restrict__ bk,
    const float* __restrict__ Wv, const float* __restrict__ bv)
{
    extern __shared__ char smemc[];
    u16* smb = (u16*)smemc;
    u32 sb = smem_u32(smemc);

    int which = blockIdx.y;
    const float* W    = (which==0) ? Wq : (which==1) ? Wk : Wv;
    const float* bias = (which==0) ? bq : (which==1) ? bk : bv;
    __nv_bfloat16* ohi = (which==0) ? g_qhi : (which==1) ? g_khi : g_vhi;
    __nv_bfloat16* olo = (which==0) ? g_qlo : (which==1) ? g_klo : g_vlo;

    int r0  = blockIdx.x * 64;
    int tid = threadIdx.x;

    for (int p = tid; p < 2048; p += 256) {
        int row = p >> 5, i = p & 31;
        float4 f = *(const float4*)(x + (size_t)(r0 + row)*CC + 4*i);
        u32 h0,l0,h1,l1;
        split2(f.x, f.y, h0, l0);
        split2(f.z, f.w, h1, l1);
        *(u64*)(smb + QX_HI + row*136 + 4*i) = ((u64)h1 << 32) | h0;
        *(u64*)(smb + QX_LO + row*136 + 4*i) = ((u64)l1 << 32) | l0;
    }
    for (int p = tid; p < 4096; p += 256) {
        int row = p >> 5, i = p & 31;
        float4 f = *(const float4*)(W + (size_t)row*CC + 4*i);
        u32 h0,l0,h1,l1;
        split2(f.x, f.y, h0, l0);
        split2(f.z, f.w, h1, l1);
        *(u64*)(smb + QW_HI + row*136 + 4*i) = ((u64)h1 << 32) | h0;
        *(u64*)(smb + QW_LO + row*136 + 4*i) = ((u64)l1 << 32) | l0;
    }
    __syncthreads();

    int wid = tid >> 5, lid = tid & 31;
    int mrow = (wid & 3) * 16;
    int ncol = (wid >> 2) * 64;
    int g = lid >> 2, t = lid & 3;

    u32 qa_hi = sb + 2u*(QX_HI + (u32)(mrow + (lid & 15))*136u + 8u*(u32)(lid >> 4));
    u32 qa_lo = qa_hi + 2u*(QX_LO - QX_HI);
    u32 kb4 = ((u32)(lid >> 4)*8u + (u32)(lid & 7))*136u + (u32)((lid >> 3) & 1)*8u;

    float acc[8][4];
#pragma unroll
    for (int j = 0; j < 8; j++)
#pragma unroll
        for (int r = 0; r < 4; r++) acc[j][r] = 0.f;

#pragma unroll
    for (int kk = 0; kk < 8; kk++) {
        u32 ah0,ah1,ah2,ah3, al0,al1,al2,al3;
        ldsm4(ah0,ah1,ah2,ah3, qa_hi + 32u*kk);
        ldsm4(al0,al1,al2,al3, qa_lo + 32u*kk);
#pragma unroll
        for (int j2 = 0; j2 < 4; j2++) {
            u32 off = 2u*((u32)(ncol + j2*16)*136u + (u32)(kk*16) + kb4);
            u32 bh0,bh1,bh2,bh3, bl0,bl1,bl2,bl3;
            ldsm4(bh0,bh1,bh2,bh3, sb + 2u*QW_HI + off);
            ldsm4(bl0,bl1,bl2,bl3, sb + 2u*QW_LO + off);
            mma16816(acc[2*j2],   ah0,ah1,ah2,ah3, bh0,bh1);
            mma16816(acc[2*j2],   ah0,ah1,ah2,ah3, bl0,bl1);
            mma16816(acc[2*j2],   al0,al1,al2,al3, bh0,bh1);
            mma16816(acc[2*j2+1], ah0,ah1,ah2,ah3, bh2,bh3);
            mma16816(acc[2*j2+1], ah0,ah1,ah2,ah3, bl2,bl3);
            mma16816(acc[2*j2+1], al0,al1,al2,al3, bh2,bh3);
        }
    }

    int row0 = r0 + mrow + g, row1 = row0 + 8;
#pragma unroll
    for (int j = 0; j < 8; j++) {
        int c = ncol + 8*j + 2*t;
        float2 bb = *(const float2*)(bias + c);
        u32 hp, lp;
        split2(acc[j][0] + bb.x, acc[j][1] + bb.y, hp, lp);
        ((u32*)ohi)[((size_t)row0*CC + c) >> 1] = hp;
        ((u32*)olo)[((size_t)row0*CC + c) >> 1] = lp;
        split2(acc[j][2] + bb.x, acc[j][3] + bb.y, hp, lp);
        ((u32*)ohi)[((size_t)row1*CC + c) >> 1] = hp;
        ((u32*)olo)[((size_t)row1*CC + c) >> 1] = lp;
    }
}

// ---------------------------------------------------------------------------
// K2: HMMA split-precision flash attention, 2 CTAs/SM for latency hiding.
// CTA: 64 q-rows, 128 threads (4 warps, warp w -> rows 16w..16w+15).
// K/V chunks of 32 rows, double-buffered via cp.async. smem 104448 B.
// ---------------------------------------------------------------------------
#define SQHI 0
#define SQLO 8704
#define SK   17408                 // + (buf*2+prec)*4352 elements
#define SV   34816                 // + (buf*2+prec)*4352
#define SMEM_EL 52224
#define SMEM_BYTES (SMEM_EL*2)     // 104448 -> 2 CTAs/SM

__device__ __forceinline__ void load_kv(char* smem_c, int node0, int buf, int tid)
{
    __nv_bfloat16* smb = (__nv_bfloat16*)smem_c;
#pragma unroll
    for (int p = tid; p < 1024; p += 128) {          // K hi/lo (32 rows)
        int prec = p >> 9, q = p & 511, row = q >> 4, i = q & 15;
        const __nv_bfloat16* src = (prec ? g_klo : g_khi) + (size_t)(node0 + row)*CC + 8*i;
        cp16(smb + SK + (buf*2 + prec)*4352 + row*136 + 8*i, src);
    }
#pragma unroll
    for (int p = tid; p < 1024; p += 128) {          // V hi/lo
        int prec = p >> 9, q = p & 511, row = q >> 4, i = q & 15;
        const __nv_bfloat16* src = (prec ? g_vlo : g_vhi) + (size_t)(node0 + row)*CC + 8*i;
        cp16(smb + SV + (buf*2 + prec)*4352 + row*136 + 8*i, src);
    }
}

__global__ __launch_bounds__(128, 2) void attn_kernel()
{
    extern __shared__ char smem[];
    __nv_bfloat16* smb = (__nv_bfloat16*)smem;
    u32 sb = smem_u32(smem);
    int tid = threadIdx.x, wid = tid >> 5, lid = tid & 31;
    int b = blockIdx.y, t0 = blockIdx.x * 64;
    int L = g_vl[b];
    int nch = (L + 31) >> 5;
    int node0 = b*TT + t0;
    int kvbase = b*TT;

    // prologue: Q hi/lo (64 rows) + chunk0 K/V
#pragma unroll
    for (int p = tid; p < 2048; p += 128) {
        int prec = p >> 10, q = p & 1023, row = q >> 4, i = q & 15;
        const __nv_bfloat16* src = (prec ? g_qlo : g_qhi) + (size_t)(node0 + row)*CC + 8*i;
        cp16(smb + (prec ? SQLO : SQHI) + row*136 + 8*i, src);
    }
    load_kv(smem, kvbase, 0, tid);
    CP_COMMIT();

    int g = lid >> 2, t = lid & 3;
    u32 qa_hi = sb + 2u*(SQHI + (u32)(16*wid + (lid & 15))*136 + 8u*(u32)(lid >> 4));
    u32 qa_lo = qa_hi + 2u*(SQLO - SQHI);
    u32 kb4 = ((u32)(lid >> 4)*8u + (u32)(lid & 7))*136u + (u32)((lid >> 3) & 1)*8u;
    u32 vr  = (u32)((lid >> 3) & 1)*8u + (u32)(lid & 7);
    u32 vc8 = (u32)(lid >> 4)*8u;

    float accO[16][4];
#pragma unroll
    for (int j = 0; j < 16; j++)
#pragma unroll
        for (int r = 0; r < 4; r++) accO[j][r] = 0.f;
    float lsum0 = 0.f, lsum1 = 0.f;

    for (int c = 0; c < nch; c++) {
        int buf = c & 1;
        if (c + 1 < nch) { load_kv(smem, kvbase + (c + 1)*32, buf ^ 1, tid); CP_COMMIT(); CP_WAIT(1); }
        else             { CP_WAIT(0); }
        __syncthreads();

        u32 sk_hi = sb + 2u*(SK + (u32)(buf*2 + 0)*4352);
        u32 sk_lo = sb + 2u*(SK + (u32)(buf*2 + 1)*4352);
        u32 sv_hi = sb + 2u*(SV + (u32)(buf*2 + 0)*4352);
        u32 sv_lo = sb + 2u*(SV + (u32)(buf*2 + 1)*4352);

        // ----- S = Q.K^T (warp: 16x32), 3-term split -----
        float accS[4][4];
#pragma unroll
        for (int j = 0; j < 4; j++)
#pragma unroll
            for (int r = 0; r < 4; r++) accS[j][r] = 0.f;

#pragma unroll
        for (int kk = 0; kk < 8; kk++) {
            u32 ah0,ah1,ah2,ah3, al0,al1,al2,al3;
            ldsm4(ah0,ah1,ah2,ah3, qa_hi + 32u*kk);
            ldsm4(al0,al1,al2,al3, qa_lo + 32u*kk);
#pragma unroll
            for (int j2 = 0; j2 < 2; j2++) {
                u32 off = 2u*((u32)(j2*16)*136u + (u32)(kk*16) + kb4);
                u32 bh0,bh1,bh2,bh3, bl0,bl1,bl2,bl3;
                ldsm4(bh0,bh1,bh2,bh3, sk_hi + off);
                ldsm4(bl0,bl1,bl2,bl3, sk_lo + off);
                mma16816(accS[2*j2],   ah0,ah1,ah2,ah3, bh0,bh1);
                mma16816(accS[2*j2],   ah0,ah1,ah2,ah3, bl0,bl1);
                mma16816(accS[2*j2],   al0,al1,al2,al3, bh0,bh1);
                mma16816(accS[2*j2+1], ah0,ah1,ah2,ah3, bh2,bh3);
                mma16816(accS[2*j2+1], ah0,ah1,ah2,ah3, bl2,bl3);
                mma16816(accS[2*j2+1], al0,al1,al2,al3, bh2,bh3);
            }
        }

        // ----- softmax (max-free) + P hi/lo repack -----
        u32 P[4][4];
        {
            int cb = c*32 + 2*t;
            float l0 = 0.f, l1 = 0.f;
#pragma unroll
            for (int j = 0; j < 4; j++) {
                int c0 = cb + 8*j;
                bool v0 = c0 < L, v1 = c0 + 1 < L;
                float p0 = v0 ? __expf(accS[j][0]) : 0.f;
                float p1 = v1 ? __expf(accS[j][1]) : 0.f;
                float p2 = v0 ? __expf(accS[j][2]) : 0.f;
                float p3 = v1 ? __expf(accS[j][3]) : 0.f;
                l0 += p0 + p1; l1 += p2 + p3;
                u32 h01 = packbf(p0, p1);
                u32 h23 = packbf(p2, p3);
                P[j][0] = h01;
                P[j][1] = h23;
                P[j][2] = packbf(p0 - bflo(h01), p1 - bfhi(h01));
                P[j][3] = packbf(p2 - bflo(h23), p3 - bfhi(h23));
            }
            lsum0 += l0; lsum1 += l1;
        }

        // ----- O += P.V (warp: 16x128), x4 trans V loads -----
#pragma unroll
        for (int kk = 0; kk < 2; kk++) {
            u32 ah0 = P[2*kk][0], ah1 = P[2*kk][1], ah2 = P[2*kk+1][0], ah3 = P[2*kk+1][1];
            u32 al0 = P[2*kk][2], al1 = P[2*kk][3], al2 = P[2*kk+1][2], al3 = P[2*kk+1][3];
            u32 rowoff = 2u*((u32)(16*kk) + vr)*136u;
#pragma unroll
            for (int j2 = 0; j2 < 8; j2++) {
                u32 off = rowoff + 2u*((u32)(16*j2) + vc8);
                u32 vh0,vh1,vh2,vh3, vl0,vl1,vl2,vl3;
                ldsm4t(vh0,vh1,vh2,vh3, sv_hi + off);
                ldsm4t(vl0,vl1,vl2,vl3, sv_lo + off);
                mma16816(accO[2*j2],   ah0,ah1,ah2,ah3, vh0,vh1);
                mma16816(accO[2*j2],   ah0,ah1,ah2,ah3, vl0,vl1);
                mma16816(accO[2*j2],   al0,al1,al2,al3, vh0,vh1);
                mma16816(accO[2*j2+1], ah0,ah1,ah2,ah3, vh2,vh3);
                mma16816(accO[2*j2+1], ah0,ah1,ah2,ah3, vl2,vl3);
                mma16816(accO[2*j2+1], al0,al1,al2,al3, vh2,vh3);
            }
        }
        __syncthreads();
    }

    // ----- epilogue -----
    lsum0 += __shfl_xor_sync(0xffffffffu, lsum0, 1);
    lsum0 += __shfl_xor_sync(0xffffffffu, lsum0, 2);
    lsum1 += __shfl_xor_sync(0xffffffffu, lsum1, 1);
    lsum1 += __shfl_xor_sync(0xffffffffu, lsum1, 2);
    float inv0 = 1.f / lsum0, inv1 = 1.f / lsum1;
    int r0 = node0 + 16*wid + g, r1 = r0 + 8;
#pragma unroll
    for (int j = 0; j < 16; j++) {
        float2 o0 = make_float2(accO[j][0]*inv0, accO[j][1]*inv0);
        float2 o1 = make_float2(accO[j][2]*inv1, accO[j][3]*inv1);
        *(float2*)(g_att + (size_t)r0*CC + 8*j + 2*t) = o0;
        *(float2*)(g_att + (size_t)r1*CC + 8*j + 2*t) = o1;
    }
}

// ---------------------------------------------------------------------------
// K3: CSR-by-dst build + gather-sum
// ---------------------------------------------------------------------------
__global__ void hist_kernel(const void* __restrict__ ei)
{
    int e = blockIdx.x*256 + threadIdx.x;
    int is64 = g_is64;
    if (e < NEDGE) {
        int d = edge_at(ei, is64, (size_t)NEDGE + e);
        atomicAdd(&g_cnt[d], 1);
    }
}
__global__ void scan_kernel()
{
    __shared__ int ssum[1024];
    int tid = threadIdx.x;
    int cnt[32];
    int s = 0;
#pragma unroll
    for (int i = 0; i < 32; i++) { cnt[i] = g_cnt[i*1024 + tid]; s += cnt[i]; }
    ssum[tid] = s;
    __syncthreads();
    for (int off = 1; off < 1024; off <<= 1) {
        int v = (tid >= off) ? ssum[tid - off] : 0;
        __syncthreads();
        ssum[tid] += v;
        __syncthreads();
    }
    int base = (tid == 0) ? 0 : ssum[tid - 1];
#pragma unroll
    for (int i = 0; i < 32; i++) {
        g_off[i*1024 + tid] = base;
        g_cur[i*1024 + tid] = base;
        base += cnt[i];
    }
}
__global__ void scatter_kernel(const void* __restrict__ ei)
{
    int e = blockIdx.x*256 + threadIdx.x;
    int is64 = g_is64;
    if (e < NEDGE) {
        int srcn = edge_at(ei, is64, (size_t)e);
        int d    = edge_at(ei, is64, (size_t)NEDGE + e);
        int p = atomicAdd(&g_cur[d], 1);
        g_csr[p] = srcn;
    }
}
__global__ void gather_kernel(float* __restrict__ out)
{
    __shared__ int srcs[512];
    int n   = blockIdx.x;
    int tid = threadIdx.x;
    int start = g_off[n];
    int cnt   = g_cnt[n];
    float acc = 0.f;
    for (int base = 0; base < cnt; base += 512) {
        int nn = min(512, cnt - base);
        for (int j = tid; j < nn; j += 128) srcs[j] = g_csr[start + base + j];
        __syncthreads();
#pragma unroll 4
        for (int j = 0; j < nn; j++)
            acc += g_att[(size_t)srcs[j]*CC + tid];
        __syncthreads();
    }
    out[(size_t)n*CC + tid] = acc;
}

// ---------------------------------------------------------------------------
// Launch (attn at index 3 for the profiler window)
// ---------------------------------------------------------------------------
extern "C" void kernel_launch(void* const* d_in, const int* in_sizes, int n_in,
                              void* d_out, int out_size)
{
    const float* x  = (const float*)d_in[0];
    const void*  ei = d_in[1];
    const int*   vl = (const int*)d_in[2];

    int wi = 3;
    while (wi < n_in && in_sizes[wi] != CC*CC) wi++;
    const float* Wq = (const float*)d_in[wi+0];
    const float* bq = (const float*)d_in[wi+1];
    const float* Wk = (const float*)d_in[wi+2];
    const float* bk = (const float*)d_in[wi+3];
    const float* Wv = (const float*)d_in[wi+4];
    const float* bv = (const float*)d_in[wi+5];
    float* out = (float*)d_out;

    cudaFuncSetAttribute(qkv_kernel,  cudaFuncAttributeMaxDynamicSharedMemorySize, QKV_SMEM_BYTES);
    cudaFuncSetAttribute(attn_kernel, cudaFuncAttributeMaxDynamicSharedMemorySize, SMEM_BYTES);

    init_kernel<<<(NNODES+255)/256, 256>>>(vl);                                       // 0
    qkv_kernel<<<dim3(NNODES/64, 3), 256, QKV_SMEM_BYTES>>>(x, Wq, bq, Wk, bk, Wv, bv); // 1
    hist_kernel<<<(NEDGE+255)/256, 256>>>(ei);                                        // 2
    attn_kernel<<<dim3(TT/64, BBATCH), 128, SMEM_BYTES>>>();                          // 3  <- profiled
    scan_kernel<<<1, 1024>>>();                                                       // 4
    scatter_kernel<<<(NEDGE+255)/256, 256>>>(ei);                                     // 5
    gather_kernel<<<NNODES, 128>>>(out);                                              // 6
}

// round 17
// speedup vs baseline: 2.9471x; 1.0347x over previous
#include <cuda_runtime.h>
#include <cuda_bf16.h>
#include <math.h>

#define CC      128
#define TT      1024
#define BBATCH  32
#define NNODES  (BBATCH*TT)      // 32768
#define NEDGE   (16*NNODES)      // 524288

typedef unsigned long long u64;
typedef unsigned int u32;
typedef unsigned short u16;

// ---------------------------------------------------------------------------
// Helpers (baseline-PTX only: cp.async, ldmatrix, mma.sync)
// ---------------------------------------------------------------------------
__device__ __forceinline__ u32 smem_u32(const void* p){
    u32 a; asm("{ .reg .u64 t; cvta.to.shared.u64 t, %1; cvt.u32.u64 %0, t; }" : "=r"(a) : "l"(p));
    return a;
}
__device__ __forceinline__ void cp16(void* dst_smem, const void* src){
    unsigned sa = (unsigned)__cvta_generic_to_shared(dst_smem);
    asm volatile("cp.async.cg.shared.global [%0], [%1], 16;" :: "r"(sa), "l"(src));
}
#define CP_COMMIT() asm volatile("cp.async.commit_group;" ::: "memory")
#define CP_WAIT(n)  asm volatile("cp.async.wait_group %0;" :: "n"(n) : "memory")

__device__ __forceinline__ void mma16816(float* c, u32 a0,u32 a1,u32 a2,u32 a3, u32 b0,u32 b1){
    asm volatile("mma.sync.aligned.m16n8k16.row.col.f32.bf16.bf16.f32 "
        "{%0,%1,%2,%3}, {%4,%5,%6,%7}, {%8,%9}, {%0,%1,%2,%3};"
        : "+f"(c[0]),"+f"(c[1]),"+f"(c[2]),"+f"(c[3])
        : "r"(a0),"r"(a1),"r"(a2),"r"(a3),"r"(b0),"r"(b1));
}
__device__ __forceinline__ void ldsm4(u32& r0,u32& r1,u32& r2,u32& r3, u32 a){
    asm volatile("ldmatrix.sync.aligned.m8n8.x4.shared.b16 {%0,%1,%2,%3}, [%4];"
        : "=r"(r0),"=r"(r1),"=r"(r2),"=r"(r3) : "r"(a));
}
__device__ __forceinline__ void ldsm4t(u32& r0,u32& r1,u32& r2,u32& r3, u32 a){
    asm volatile("ldmatrix.sync.aligned.m8n8.x4.trans.shared.b16 {%0,%1,%2,%3}, [%4];"
        : "=r"(r0),"=r"(r1),"=r"(r2),"=r"(r3) : "r"(a));
}
__device__ __forceinline__ u32 packbf(float lo, float hi){
    u32 d; asm("cvt.rn.bf16x2.f32 %0, %1, %2;" : "=r"(d) : "f"(hi), "f"(lo)); return d;
}
__device__ __forceinline__ float bflo(u32 v){
    return __bfloat162float(__ushort_as_bfloat16((u16)(v & 0xffffu)));
}
__device__ __forceinline__ float bfhi(u32 v){
    return __bfloat162float(__ushort_as_bfloat16((u16)(v >> 16)));
}
__device__ __forceinline__ void split2(float v0, float v1, u32& hp, u32& lp){
    hp = packbf(v0, v1);
    lp = packbf(v0 - bflo(hp), v1 - bfhi(hp));
}

// ---------------------------------------------------------------------------
// Device scratch
// ---------------------------------------------------------------------------
__device__ __nv_bfloat16 g_qhi[NNODES*CC], g_qlo[NNODES*CC];
__device__ __nv_bfloat16 g_khi[NNODES*CC], g_klo[NNODES*CC];
__device__ __nv_bfloat16 g_vhi[NNODES*CC], g_vlo[NNODES*CC];
__device__ float g_att[NNODES*CC];
__device__ int   g_cnt[NNODES], g_off[NNODES], g_cur[NNODES], g_csr[NEDGE];
__device__ int   g_vl[BBATCH], g_is64;

// ---------------------------------------------------------------------------
// K0: fused init: sniff dtype + normalize valid_lens (block 0) + zero cnt
// ---------------------------------------------------------------------------
__global__ void init_kernel(const int* __restrict__ vl_raw)
{
    int i = blockIdx.x*256 + threadIdx.x;
    if (i < NNODES) g_cnt[i] = 0;
    if (blockIdx.x == 0 && threadIdx.x == 0) {
        bool is64 = true;
        for (int j = 0; j < BBATCH; j++)
            if (vl_raw[2*j + 1] != 0) { is64 = false; break; }
        g_is64 = is64 ? 1 : 0;
        for (int j = 0; j < BBATCH; j++)
            g_vl[j] = is64 ? vl_raw[2*j] : vl_raw[j];
    }
}
__device__ __forceinline__ int edge_at(const void* ei, int is64, size_t idx)
{
    return is64 ? (int)((const long long*)ei)[idx] : ((const int*)ei)[idx];
}

// ---------------------------------------------------------------------------
// K1: qkv projection via HMMA split precision (frozen from R14)
// ---------------------------------------------------------------------------
#define QX_HI 0
#define QX_LO 8704
#define QW_HI 17408
#define QW_LO 34816
#define QKV_SMEM_EL 52224
#define QKV_SMEM_BYTES (QKV_SMEM_EL*2)   // 104448 -> 2 CTAs/SM

__global__ __launch_bounds__(256, 2) void qkv_kernel(
    const float* __restrict__ x,
    const float* __restrict__ Wq, const float* __restrict__ bq,
    const float* __restrict__ Wk, const float* __restrict__ bk,
    const float* __restrict__ Wv, const float* __restrict__ bv)
{
    extern __shared__ char smemc[];
    u16* smb = (u16*)smemc;
    u32 sb = smem_u32(smemc);

    int which = blockIdx.y;
    const float* W    = (which==0) ? Wq : (which==1) ? Wk : Wv;
    const float* bias = (which==0) ? bq : (which==1) ? bk : bv;
    __nv_bfloat16* ohi = (which==0) ? g_qhi : (which==1) ? g_khi : g_vhi;
    __nv_bfloat16* olo = (which==0) ? g_qlo : (which==1) ? g_klo : g_vlo;

    int r0  = blockIdx.x * 64;
    int tid = threadIdx.x;

    for (int p = tid; p < 2048; p += 256) {
        int row = p >> 5, i = p & 31;
        float4 f = *(const float4*)(x + (size_t)(r0 + row)*CC + 4*i);
        u32 h0,l0,h1,l1;
        split2(f.x, f.y, h0, l0);
        split2(f.z, f.w, h1, l1);
        *(u64*)(smb + QX_HI + row*136 + 4*i) = ((u64)h1 << 32) | h0;
        *(u64*)(smb + QX_LO + row*136 + 4*i) = ((u64)l1 << 32) | l0;
    }
    for (int p = tid; p < 4096; p += 256) {
        int row = p >> 5, i = p & 31;
        float4 f = *(const float4*)(W + (size_t)row*CC + 4*i);
        u32 h0,l0,h1,l1;
        split2(f.x, f.y, h0, l0);
        split2(f.z, f.w, h1, l1);
        *(u64*)(smb + QW_HI + row*136 + 4*i) = ((u64)h1 << 32) | h0;
        *(u64*)(smb + QW_LO + row*136 + 4*i) = ((u64)l1 << 32) | l0;
    }
    __syncthreads();

    int wid = tid >> 5, lid = tid & 31;
    int mrow = (wid & 3) * 16;
    int ncol = (wid >> 2) * 64;
    int g = lid >> 2, t = lid & 3;

    u32 qa_hi = sb + 2u*(QX_HI + (u32)(mrow + (lid & 15))*136u + 8u*(u32)(lid >> 4));
    u32 qa_lo = qa_hi + 2u*(QX_LO - QX_HI);
    u32 kb4 = ((u32)(lid >> 4)*8u + (u32)(lid & 7))*136u + (u32)((lid >> 3) & 1)*8u;

    float acc[8][4];
#pragma unroll
    for (int j = 0; j < 8; j++)
#pragma unroll
        for (int r = 0; r < 4; r++) acc[j][r] = 0.f;

#pragma unroll
    for (int kk = 0; kk < 8; kk++) {
        u32 ah0,ah1,ah2,ah3, al0,al1,al2,al3;
        ldsm4(ah0,ah1,ah2,ah3, qa_hi + 32u*kk);
        ldsm4(al0,al1,al2,al3, qa_lo + 32u*kk);
#pragma unroll
        for (int j2 = 0; j2 < 4; j2++) {
            u32 off = 2u*((u32)(ncol + j2*16)*136u + (u32)(kk*16) + kb4);
            u32 bh0,bh1,bh2,bh3, bl0,bl1,bl2,bl3;
            ldsm4(bh0,bh1,bh2,bh3, sb + 2u*QW_HI + off);
            ldsm4(bl0,bl1,bl2,bl3, sb + 2u*QW_LO + off);
            mma16816(acc[2*j2],   ah0,ah1,ah2,ah3, bh0,bh1);
            mma16816(acc[2*j2],   ah0,ah1,ah2,ah3, bl0,bl1);
            mma16816(acc[2*j2],   al0,al1,al2,al3, bh0,bh1);
            mma16816(acc[2*j2+1], ah0,ah1,ah2,ah3, bh2,bh3);
            mma16816(acc[2*j2+1], ah0,ah1,ah2,ah3, bl2,bl3);
            mma16816(acc[2*j2+1], al0,al1,al2,al3, bh2,bh3);
        }
    }

    int row0 = r0 + mrow + g, row1 = row0 + 8;
#pragma unroll
    for (int j = 0; j < 8; j++) {
        int c = ncol + 8*j + 2*t;
        float2 bb = *(const float2*)(bias + c);
        u32 hp, lp;
        split2(acc[j][0] + bb.x, acc[j][1] + bb.y, hp, lp);
        ((u32*)ohi)[((size_t)row0*CC + c) >> 1] = hp;
        ((u32*)olo)[((size_t)row0*CC + c) >> 1] = lp;
        split2(acc[j][2] + bb.x, acc[j][3] + bb.y, hp, lp);
        ((u32*)ohi)[((size_t)row1*CC + c) >> 1] = hp;
        ((u32*)olo)[((size_t)row1*CC + c) >> 1] = lp;
    }
}

// ---------------------------------------------------------------------------
// K2: HMMA split-precision flash attention, SOFTWARE-PIPELINED:
// S(c+1) computed while softmax(c)+PV(c) consume last iteration's scores.
// CTA: 64 q-rows, 128 threads. K 2-buf, V 3-buf, Qlo fragments in registers.
// smem: Qhi 8704 el | K 2x8704 | V 3x8704 = 52224 el = 104448 B -> 2 CTAs/SM.
// ---------------------------------------------------------------------------
#define SQHI 0
#define SKB  8704                  // K buf b: SKB + b*8704 (hi), +4352 (lo)
#define SVB  26112                 // V buf b: SVB + b*8704 (hi), +4352 (lo)
#define SMEM_EL 52224
#define SMEM_BYTES (SMEM_EL*2)     // 104448

__device__ __forceinline__ void load_k(char* smem_c, int node0, int buf, int tid)
{
    __nv_bfloat16* smb = (__nv_bfloat16*)smem_c;
#pragma unroll
    for (int p = tid; p < 1024; p += 128) {
        int prec = p >> 9, q = p & 511, row = q >> 4, i = q & 15;
        const __nv_bfloat16* src = (prec ? g_klo : g_khi) + (size_t)(node0 + row)*CC + 8*i;
        cp16(smb + SKB + buf*8704 + prec*4352 + row*136 + 8*i, src);
    }
}
__device__ __forceinline__ void load_v(char* smem_c, int node0, int buf, int tid)
{
    __nv_bfloat16* smb = (__nv_bfloat16*)smem_c;
#pragma unroll
    for (int p = tid; p < 1024; p += 128) {
        int prec = p >> 9, q = p & 511, row = q >> 4, i = q & 15;
        const __nv_bfloat16* src = (prec ? g_vlo : g_vhi) + (size_t)(node0 + row)*CC + 8*i;
        cp16(smb + SVB + buf*8704 + prec*4352 + row*136 + 8*i, src);
    }
}

// S = Q.K^T for one 32-row chunk (warp: 16x32), 3-term bf16 split.
__device__ __forceinline__ void s_chunk(
    float (&accS)[4][4], u32 sk_hi, u32 sk_lo, u32 qa_hi,
    const u32 (&qlo)[32], u32 kb4)
{
#pragma unroll
    for (int j = 0; j < 4; j++)
#pragma unroll
        for (int r = 0; r < 4; r++) accS[j][r] = 0.f;
#pragma unroll
    for (int kk = 0; kk < 8; kk++) {
        u32 ah0,ah1,ah2,ah3;
        ldsm4(ah0,ah1,ah2,ah3, qa_hi + 32u*kk);
        u32 al0 = qlo[4*kk], al1 = qlo[4*kk+1], al2 = qlo[4*kk+2], al3 = qlo[4*kk+3];
#pragma unroll
        for (int j2 = 0; j2 < 2; j2++) {
            u32 off = 2u*((u32)(j2*16)*136u + (u32)(kk*16) + kb4);
            u32 bh0,bh1,bh2,bh3, bl0,bl1,bl2,bl3;
            ldsm4(bh0,bh1,bh2,bh3, sk_hi + off);
            ldsm4(bl0,bl1,bl2,bl3, sk_lo + off);
            mma16816(accS[2*j2],   ah0,ah1,ah2,ah3, bh0,bh1);
            mma16816(accS[2*j2],   ah0,ah1,ah2,ah3, bl0,bl1);
            mma16816(accS[2*j2],   al0,al1,al2,al3, bh0,bh1);
            mma16816(accS[2*j2+1], ah0,ah1,ah2,ah3, bh2,bh3);
            mma16816(accS[2*j2+1], ah0,ah1,ah2,ah3, bl2,bl3);
            mma16816(accS[2*j2+1], al0,al1,al2,al3, bh2,bh3);
        }
    }
}

// softmax (max-free) on accS of chunk c, then O += P.V
__device__ __forceinline__ void soft_pv(
    float (&accS)[4][4], int c, int L, u32 sv_hi, u32 sv_lo,
    u32 vr, u32 vc8, int t, float (&accO)[16][4], float& lsum0, float& lsum1)
{
    u32 P[4][4];
    {
        int cb = c*32 + 2*t;
        float l0 = 0.f, l1 = 0.f;
#pragma unroll
        for (int j = 0; j < 4; j++) {
            int c0 = cb + 8*j;
            bool v0 = c0 < L, v1 = c0 + 1 < L;
            float p0 = v0 ? __expf(accS[j][0]) : 0.f;
            float p1 = v1 ? __expf(accS[j][1]) : 0.f;
            float p2 = v0 ? __expf(accS[j][2]) : 0.f;
            float p3 = v1 ? __expf(accS[j][3]) : 0.f;
            l0 += p0 + p1; l1 += p2 + p3;
            u32 h01 = packbf(p0, p1);
            u32 h23 = packbf(p2, p3);
            P[j][0] = h01;
            P[j][1] = h23;
            P[j][2] = packbf(p0 - bflo(h01), p1 - bfhi(h01));
            P[j][3] = packbf(p2 - bflo(h23), p3 - bfhi(h23));
        }
        lsum0 += l0; lsum1 += l1;
    }
#pragma unroll
    for (int kk = 0; kk < 2; kk++) {
        u32 ah0 = P[2*kk][0], ah1 = P[2*kk][1], ah2 = P[2*kk+1][0], ah3 = P[2*kk+1][1];
        u32 al0 = P[2*kk][2], al1 = P[2*kk][3], al2 = P[2*kk+1][2], al3 = P[2*kk+1][3];
        u32 rowoff = 2u*((u32)(16*kk) + vr)*136u;
#pragma unroll
        for (int j2 = 0; j2 < 8; j2++) {
            u32 off = rowoff + 2u*((u32)(16*j2) + vc8);
            u32 vh0,vh1,vh2,vh3, vl0,vl1,vl2,vl3;
            ldsm4t(vh0,vh1,vh2,vh3, sv_hi + off);
            ldsm4t(vl0,vl1,vl2,vl3, sv_lo + off);
            mma16816(accO[2*j2],   ah0,ah1,ah2,ah3, vh0,vh1);
            mma16816(accO[2*j2],   ah0,ah1,ah2,ah3, vl0,vl1);
            mma16816(accO[2*j2],   al0,al1,al2,al3, vh0,vh1);
            mma16816(accO[2*j2+1], ah0,ah1,ah2,ah3, vh2,vh3);
            mma16816(accO[2*j2+1], ah0,ah1,ah2,ah3, vl2,vl3);
            mma16816(accO[2*j2+1], al0,al1,al2,al3, vh2,vh3);
        }
    }
}

__global__ __launch_bounds__(128, 2) void attn_kernel()
{
    extern __shared__ char smem[];
    __nv_bfloat16* smb = (__nv_bfloat16*)smem;
    u32 sb = smem_u32(smem);
    int tid = threadIdx.x, wid = tid >> 5, lid = tid & 31;
    int b = blockIdx.y, t0 = blockIdx.x * 64;
    int L = g_vl[b];
    int nch = (L + 31) >> 5;
    int node0 = b*TT + t0;
    int kvbase = b*TT;

    // ---- prologue group A: Qhi, Qlo(staged in V buf 2), K0, V0 ----
#pragma unroll
    for (int p = tid; p < 1024; p += 128) {
        int row = p >> 4, i = p & 15;
        cp16(smb + SQHI + row*136 + 8*i, g_qhi + (size_t)(node0 + row)*CC + 8*i);
    }
#pragma unroll
    for (int p = tid; p < 1024; p += 128) {
        int row = p >> 4, i = p & 15;
        cp16(smb + SVB + 2*8704 + row*136 + 8*i, g_qlo + (size_t)(node0 + row)*CC + 8*i);
    }
    load_k(smem, kvbase, 0, tid);
    load_v(smem, kvbase, 0, tid);
    CP_COMMIT();
    CP_WAIT(0);
    __syncthreads();

    int g = lid >> 2, t = lid & 3;
    u32 qa_hi = sb + 2u*(SQHI + (u32)(16*wid + (lid & 15))*136 + 8u*(u32)(lid >> 4));
    u32 qa_lo = sb + 2u*(SVB + 2*8704 + (u32)(16*wid + (lid & 15))*136 + 8u*(u32)(lid >> 4));
    u32 kb4 = ((u32)(lid >> 4)*8u + (u32)(lid & 7))*136u + (u32)((lid >> 3) & 1)*8u;
    u32 vr  = (u32)((lid >> 3) & 1)*8u + (u32)(lid & 7);
    u32 vc8 = (u32)(lid >> 4)*8u;

    // hoist Qlo fragments to registers (staging area reused as V buf 2 later)
    u32 qlo[32];
#pragma unroll
    for (int kk = 0; kk < 8; kk++)
        ldsm4(qlo[4*kk], qlo[4*kk+1], qlo[4*kk+2], qlo[4*kk+3], qa_lo + 32u*kk);

    // group B: K1, V1 (waited at top of iteration 0)
    if (nch > 1) { load_k(smem, kvbase + 32, 1, tid); load_v(smem, kvbase + 32, 1, tid); CP_COMMIT(); }

    float accO[16][4];
#pragma unroll
    for (int j = 0; j < 16; j++)
#pragma unroll
        for (int r = 0; r < 4; r++) accO[j][r] = 0.f;
    float lsum0 = 0.f, lsum1 = 0.f;
    float accSa[4][4], accSb[4][4];

    // S(0) -> accSa
    s_chunk(accSa, sb + 2u*SKB, sb + 2u*(SKB + 4352), qa_hi, qlo, kb4);

    for (int c = 0; c < nch; c++) {
        CP_WAIT(0);
        __syncthreads();
        if (c + 2 < nch) {     // prefetch chunk c+2 (lands during iteration c+1)
            load_k(smem, kvbase + (c+2)*32, c & 1, tid);
            load_v(smem, kvbase + (c+2)*32, (c+2) % 3, tid);
            CP_COMMIT();
        }
        u32 skb = sb + 2u*(SKB + (u32)(((c+1) & 1))*8704u);
        u32 svb = sb + 2u*(SVB + (u32)(c % 3)*8704u);
        if ((c & 1) == 0) {
            if (c + 1 < nch) s_chunk(accSb, skb, skb + 2u*4352u, qa_hi, qlo, kb4);
            soft_pv(accSa, c, L, svb, svb + 2u*4352u, vr, vc8, t, accO, lsum0, lsum1);
        } else {
            if (c + 1 < nch) s_chunk(accSa, skb, skb + 2u*4352u, qa_hi, qlo, kb4);
            soft_pv(accSb, c, L, svb, svb + 2u*4352u, vr, vc8, t, accO, lsum0, lsum1);
        }
    }

    // ---- epilogue ----
    lsum0 += __shfl_xor_sync(0xffffffffu, lsum0, 1);
    lsum0 += __shfl_xor_sync(0xffffffffu, lsum0, 2);
    lsum1 += __shfl_xor_sync(0xffffffffu, lsum1, 1);
    lsum1 += __shfl_xor_sync(0xffffffffu, lsum1, 2);
    float inv0 = 1.f / lsum0, inv1 = 1.f / lsum1;
    int r0 = node0 + 16*wid + g, r1 = r0 + 8;
#pragma unroll
    for (int j = 0; j < 16; j++) {
        float2 o0 = make_float2(accO[j][0]*inv0, accO[j][1]*inv0);
        float2 o1 = make_float2(accO[j][2]*inv1, accO[j][3]*inv1);
        *(float2*)(g_att + (size_t)r0*CC + 8*j + 2*t) = o0;
        *(float2*)(g_att + (size_t)r1*CC + 8*j + 2*t) = o1;
    }
}

// ---------------------------------------------------------------------------
// K3: CSR-by-dst build + gather-sum
// ---------------------------------------------------------------------------
__global__ void hist_kernel(const void* __restrict__ ei)
{
    int e = blockIdx.x*256 + threadIdx.x;
    int is64 = g_is64;
    if (e < NEDGE) {
        int d = edge_at(ei, is64, (size_t)NEDGE + e);
        atomicAdd(&g_cnt[d], 1);
    }
}
__global__ void scan_kernel()
{
    __shared__ int ssum[1024];
    int tid = threadIdx.x;
    int cnt[32];
    int s = 0;
#pragma unroll
    for (int i = 0; i < 32; i++) { cnt[i] = g_cnt[i*1024 + tid]; s += cnt[i]; }
    ssum[tid] = s;
    __syncthreads();
    for (int off = 1; off < 1024; off <<= 1) {
        int v = (tid >= off) ? ssum[tid - off] : 0;
        __syncthreads();
        ssum[tid] += v;
        __syncthreads();
    }
    int base = (tid == 0) ? 0 : ssum[tid - 1];
#pragma unroll
    for (int i = 0; i < 32; i++) {
        g_off[i*1024 + tid] = base;
        g_cur[i*1024 + tid] = base;
        base += cnt[i];
    }
}
__global__ void scatter_kernel(const void* __restrict__ ei)
{
    int e = blockIdx.x*256 + threadIdx.x;
    int is64 = g_is64;
    if (e < NEDGE) {
        int srcn = edge_at(ei, is64, (size_t)e);
        int d    = edge_at(ei, is64, (size_t)NEDGE + e);
        int p = atomicAdd(&g_cur[d], 1);
        g_csr[p] = srcn;
    }
}
__global__ void gather_kernel(float* __restrict__ out)
{
    __shared__ int srcs[512];
    int n   = blockIdx.x;
    int tid = threadIdx.x;
    int start = g_off[n];
    int cnt   = g_cnt[n];
    float acc = 0.f;
    for (int base = 0; base < cnt; base += 512) {
        int nn = min(512, cnt - base);
        for (int j = tid; j < nn; j += 128) srcs[j] = g_csr[start + base + j];
        __syncthreads();
#pragma unroll 4
        for (int j = 0; j < nn; j++)
            acc += g_att[(size_t)srcs[j]*CC + tid];
        __syncthreads();
    }
    out[(size_t)n*CC + tid] = acc;
}

// ---------------------------------------------------------------------------
// Launch (attn at index 3 for the profiler window)
// ---------------------------------------------------------------------------
extern "C" void kernel_launch(void* const* d_in, const int* in_sizes, int n_in,
                              void* d_out, int out_size)
{
    const float* x  = (const float*)d_in[0];
    const void*  ei = d_in[1];
    const int*   vl = (const int*)d_in[2];

    int wi = 3;
    while (wi < n_in && in_sizes[wi] != CC*CC) wi++;
    const float* Wq = (const float*)d_in[wi+0];
    const float* bq = (const float*)d_in[wi+1];
    const float* Wk = (const float*)d_in[wi+2];
    const float* bk = (const float*)d_in[wi+3];
    const float* Wv = (const float*)d_in[wi+4];
    const float* bv = (const float*)d_in[wi+5];
    float* out = (float*)d_out;

    cudaFuncSetAttribute(qkv_kernel,  cudaFuncAttributeMaxDynamicSharedMemorySize, QKV_SMEM_BYTES);
    cudaFuncSetAttribute(attn_kernel, cudaFuncAttributeMaxDynamicSharedMemorySize, SMEM_BYTES);

    init_kernel<<<(NNODES+255)/256, 256>>>(vl);                                       // 0
    qkv_kernel<<<dim3(NNODES/64, 3), 256, QKV_SMEM_BYTES>>>(x, Wq, bq, Wk, bk, Wv, bv); // 1
    hist_kernel<<<(NEDGE+255)/256, 256>>>(ei);                                        // 2
    attn_kernel<<<dim3(TT/64, BBATCH), 128, SMEM_BYTES>>>();                          // 3  <- profiled
    scan_kernel<<<1, 1024>>>();                                                       // 4
    scatter_kernel<<<(NEDGE+255)/256, 256>>>(ei);                                     // 5
    gather_kernel<<<NNODES, 128>>>(out);                                              // 6
}